// round 1
// baseline (speedup 1.0000x reference)
#include <cuda_runtime.h>
#include <math.h>

#define NIMG 8
#define CS   128
#define CT   256
#define HWD  64
#define PIX  4096           // 64*64
#define NPIX (NIMG*PIX)     // 32768
#define DTOT (CT*PIX)       // 1048576 per image

// ---- scratch (allocation-free rule: __device__ globals) ----
__device__ float g_masked[(size_t)NIMG*CT*PIX];
__device__ float g_g1[(size_t)NIMG*CT*PIX];
__device__ float g_t[(size_t)NIMG*CT*PIX];
__device__ double g_acc[72];   // [0..63] dots[i][j], [64..71] ||t_j||^2

__global__ void init_kernel() {
    if (threadIdx.x < 72) g_acc[threadIdx.x] = 0.0;
}

// =====================================================================
// conv 1x1 (channel align) + checkerboard mask, GEMM M=256,K=128,N=32768
// tile 128x128, Kstep 8, 256 threads, 8x8 per thread
// =====================================================================
__global__ __launch_bounds__(256)
void conv1x1_mask_kernel(const float* __restrict__ S, const float* __restrict__ W,
                         const float* __restrict__ bias, float* __restrict__ out) {
    __shared__ float As[2][8][132];
    __shared__ float Bs[2][8][128];
    const int tid  = threadIdx.x;
    const int m0   = blockIdx.y * 128;
    const int n0   = blockIdx.x * 128;
    const int img  = n0 >> 12;
    const int pix0 = n0 & 4095;

    const int a_m  = tid >> 1;
    const int a_k4 = (tid & 1) << 2;
    const float* Arow = W + (m0 + a_m) * CS + a_k4;

    const int b_n  = tid & 127;
    const int b_k0 = (tid >> 7) << 2;
    const float* Sim = S + (size_t)img * CS * PIX + pix0 + b_n;

    float acc[8][8];
#pragma unroll
    for (int i = 0; i < 8; i++)
#pragma unroll
        for (int j = 0; j < 8; j++) acc[i][j] = 0.f;

    const int KSTEPS = CS / 8;   // 16

    // prologue: load step 0 into buf 0
    {
        float4 v = *(const float4*)(Arow);
        As[0][a_k4+0][a_m] = v.x; As[0][a_k4+1][a_m] = v.y;
        As[0][a_k4+2][a_m] = v.z; As[0][a_k4+3][a_m] = v.w;
#pragma unroll
        for (int i = 0; i < 4; i++) {
            int ci = b_k0 + i;
            Bs[0][b_k0+i][b_n] = Sim[(size_t)ci * PIX];
        }
    }
    __syncthreads();

    for (int ks = 0; ks < KSTEPS; ks++) {
        const int buf = ks & 1;
        if (ks + 1 < KSTEPS) {
            float4 v = *(const float4*)(Arow + (ks+1)*8);
            As[buf^1][a_k4+0][a_m] = v.x; As[buf^1][a_k4+1][a_m] = v.y;
            As[buf^1][a_k4+2][a_m] = v.z; As[buf^1][a_k4+3][a_m] = v.w;
#pragma unroll
            for (int i = 0; i < 4; i++) {
                int ci = (ks+1)*8 + b_k0 + i;
                Bs[buf^1][b_k0+i][b_n] = Sim[(size_t)ci * PIX];
            }
        }
#pragma unroll
        for (int kk = 0; kk < 8; kk++) {
            float a[8], b[8];
            *(float4*)&a[0] = *(const float4*)&As[buf][kk][(tid>>4)*8];
            *(float4*)&a[4] = *(const float4*)&As[buf][kk][(tid>>4)*8+4];
            *(float4*)&b[0] = *(const float4*)&Bs[buf][kk][(tid&15)*8];
            *(float4*)&b[4] = *(const float4*)&Bs[buf][kk][(tid&15)*8+4];
#pragma unroll
            for (int i = 0; i < 8; i++)
#pragma unroll
                for (int j = 0; j < 8; j++)
                    acc[i][j] = fmaf(a[i], b[j], acc[i][j]);
        }
        __syncthreads();
    }

    // epilogue: bias + checkerboard mask ((h+w)%2), write
    const int mt   = (tid >> 4) << 3;
    const int nt   = (tid & 15) << 3;
    const int pixb = pix0 + nt;
    const int hh   = pixb >> 6;
    const int ww0  = pixb & 63;
    float* obase = out + (size_t)img * CT * PIX + (size_t)(m0 + mt) * PIX + pixb;
#pragma unroll
    for (int i = 0; i < 8; i++) {
        float bi = bias[m0 + mt + i];
        float v[8];
#pragma unroll
        for (int j = 0; j < 8; j++) {
            int par = (hh + ww0 + j) & 1;
            v[j] = par ? (acc[i][j] + bi) : 0.f;
        }
        float* o = obase + (size_t)i * PIX;
        *(float4*)(o)     = *(float4*)&v[0];
        *(float4*)(o + 4) = *(float4*)&v[4];
    }
}

// =====================================================================
// conv 3x3 pad=1 as implicit GEMM: M=256, K=Ci*9=2304, N=32768
// weights row-major [Co, Ci*9] (native [Co,Ci,3,3] layout)
// =====================================================================
template<bool RELU>
__global__ __launch_bounds__(256)
void conv3x3_kernel(const float* __restrict__ in, const float* __restrict__ Wt,
                    const float* __restrict__ bias, float* __restrict__ out) {
    __shared__ float As[2][8][132];
    __shared__ float Bs[2][8][128];
    const int tid  = threadIdx.x;
    const int m0   = blockIdx.y * 128;
    const int n0   = blockIdx.x * 128;
    const int img  = n0 >> 12;
    const int pix0 = n0 & 4095;
    const int h0   = pix0 >> 6;

    const int a_m  = tid >> 1;
    const int a_k4 = (tid & 1) << 2;
    const float* Arow = Wt + (size_t)(m0 + a_m) * (CT*9) + a_k4;

    const int b_n  = tid & 127;
    const int b_k0 = (tid >> 7) << 2;
    const int hh   = h0 + (b_n >> 6);
    const int ww   = b_n & 63;
    const float* inImg = in + (size_t)img * CT * PIX;

    float acc[8][8];
#pragma unroll
    for (int i = 0; i < 8; i++)
#pragma unroll
        for (int j = 0; j < 8; j++) acc[i][j] = 0.f;

    const int KSTEPS = (CT*9) / 8;  // 288

    // prologue
    {
        float4 v = *(const float4*)(Arow);
        As[0][a_k4+0][a_m] = v.x; As[0][a_k4+1][a_m] = v.y;
        As[0][a_k4+2][a_m] = v.z; As[0][a_k4+3][a_m] = v.w;
#pragma unroll
        for (int i = 0; i < 4; i++) {
            int k  = b_k0 + i;
            int ci = k / 9, r = k % 9;
            int h  = hh + r/3 - 1, w = ww + r%3 - 1;
            float val = 0.f;
            if ((unsigned)h < 64u && (unsigned)w < 64u)
                val = __ldg(inImg + (size_t)ci*PIX + h*HWD + w);
            Bs[0][b_k0+i][b_n] = val;
        }
    }
    __syncthreads();

    for (int ks = 0; ks < KSTEPS; ks++) {
        const int buf = ks & 1;
        if (ks + 1 < KSTEPS) {
            float4 v = *(const float4*)(Arow + (ks+1)*8);
            As[buf^1][a_k4+0][a_m] = v.x; As[buf^1][a_k4+1][a_m] = v.y;
            As[buf^1][a_k4+2][a_m] = v.z; As[buf^1][a_k4+3][a_m] = v.w;
#pragma unroll
            for (int i = 0; i < 4; i++) {
                int k  = (ks+1)*8 + b_k0 + i;
                int ci = k / 9, r = k % 9;
                int h  = hh + r/3 - 1, w = ww + r%3 - 1;
                float val = 0.f;
                if ((unsigned)h < 64u && (unsigned)w < 64u)
                    val = __ldg(inImg + (size_t)ci*PIX + h*HWD + w);
                Bs[buf^1][b_k0+i][b_n] = val;
            }
        }
#pragma unroll
        for (int kk = 0; kk < 8; kk++) {
            float a[8], b[8];
            *(float4*)&a[0] = *(const float4*)&As[buf][kk][(tid>>4)*8];
            *(float4*)&a[4] = *(const float4*)&As[buf][kk][(tid>>4)*8+4];
            *(float4*)&b[0] = *(const float4*)&Bs[buf][kk][(tid&15)*8];
            *(float4*)&b[4] = *(const float4*)&Bs[buf][kk][(tid&15)*8+4];
#pragma unroll
            for (int i = 0; i < 8; i++)
#pragma unroll
                for (int j = 0; j < 8; j++)
                    acc[i][j] = fmaf(a[i], b[j], acc[i][j]);
        }
        __syncthreads();
    }

    const int mt   = (tid >> 4) << 3;
    const int nt   = (tid & 15) << 3;
    const int pixb = pix0 + nt;
    float* obase = out + (size_t)img * CT * PIX + (size_t)(m0 + mt) * PIX + pixb;
#pragma unroll
    for (int i = 0; i < 8; i++) {
        float bi = bias[m0 + mt + i];
        float v[8];
#pragma unroll
        for (int j = 0; j < 8; j++) {
            float x = acc[i][j] + bi;
            if (RELU) x = fmaxf(x, 0.f);
            v[j] = x;
        }
        float* o = obase + (size_t)i * PIX;
        *(float4*)(o)     = *(float4*)&v[0];
        *(float4*)(o + 4) = *(float4*)&v[4];
    }
}

// =====================================================================
// pairwise dots: dots[i][j] = p_i . t_j ; tn[j] = ||t_j||^2
// 512 blocks x 256 threads, 2048 d-elements per block
// =====================================================================
__global__ __launch_bounds__(256)
void dot_kernel(const float* __restrict__ p, const float* __restrict__ t) {
    const int tid = threadIdx.x;
    const int d0  = blockIdx.x * 2048 + tid;

    float dacc[8][8];
    float tn[8];
#pragma unroll
    for (int i = 0; i < 8; i++) {
        tn[i] = 0.f;
#pragma unroll
        for (int j = 0; j < 8; j++) dacc[i][j] = 0.f;
    }

#pragma unroll 2
    for (int it = 0; it < 8; it++) {
        int d = d0 + it * 256;
        float pv[8], tv[8];
#pragma unroll
        for (int i = 0; i < 8; i++) {
            pv[i] = __ldg(p + (size_t)i * DTOT + d);
            tv[i] = __ldg(t + (size_t)i * DTOT + d);
        }
#pragma unroll
        for (int j = 0; j < 8; j++) tn[j] = fmaf(tv[j], tv[j], tn[j]);
#pragma unroll
        for (int i = 0; i < 8; i++)
#pragma unroll
            for (int j = 0; j < 8; j++)
                dacc[i][j] = fmaf(pv[i], tv[j], dacc[i][j]);
    }

    __shared__ float red[8][72];
    const int lane = tid & 31, warp = tid >> 5;
#pragma unroll
    for (int i = 0; i < 8; i++)
#pragma unroll
        for (int j = 0; j < 8; j++) {
            float v = dacc[i][j];
#pragma unroll
            for (int s = 16; s; s >>= 1) v += __shfl_xor_sync(0xFFFFFFFFu, v, s);
            if (lane == 0) red[warp][i*8+j] = v;
        }
#pragma unroll
    for (int j = 0; j < 8; j++) {
        float v = tn[j];
#pragma unroll
        for (int s = 16; s; s >>= 1) v += __shfl_xor_sync(0xFFFFFFFFu, v, s);
        if (lane == 0) red[warp][64+j] = v;
    }
    __syncthreads();
    if (tid < 72) {
        double s = 0.0;
#pragma unroll
        for (int w = 0; w < 8; w++) s += (double)red[w][tid];
        atomicAdd(&g_acc[tid], s);
    }
}

// =====================================================================
// finalize: reduced logits L[i][j] = (dot - 0.5*tn_j)/64 (||p_i||^2 is
// constant per row and cancels exactly in logsumexp - diag)
// =====================================================================
__global__ void finalize_kernel(float* __restrict__ out) {
    if (threadIdx.x != 0 || blockIdx.x != 0) return;
    double L[8][8];
    for (int i = 0; i < 8; i++)
        for (int j = 0; j < 8; j++)
            L[i][j] = (g_acc[i*8+j] - 0.5 * g_acc[64+j]) / 64.0;
    double ce = 0.0;
    for (int i = 0; i < 8; i++) {
        double m = L[i][0];
        for (int j = 1; j < 8; j++) m = L[i][j] > m ? L[i][j] : m;
        double s = 0.0;
        for (int j = 0; j < 8; j++) s += exp(L[i][j] - m);
        ce += (m + log(s)) - L[i][i];
    }
    ce /= 8.0;
    double loss = ce * (2.0 * 64.0 / 8.0) * 2e-05;
    out[0] = (float)loss;
}

// =====================================================================
extern "C" void kernel_launch(void* const* d_in, const int* in_sizes, int n_in,
                              void* d_out, int out_size) {
    const float* S  = (const float*)d_in[0];  // preds_S [8,128,64,64]
    const float* T  = (const float*)d_in[1];  // preds_T [8,256,64,64]
    const float* Wa = (const float*)d_in[2];  // [256,128,1,1]
    const float* ba = (const float*)d_in[3];  // [256]
    const float* W1 = (const float*)d_in[4];  // [256,256,3,3]
    const float* b1 = (const float*)d_in[5];
    const float* W2 = (const float*)d_in[6];
    const float* b2 = (const float*)d_in[7];
    float* out = (float*)d_out;

    float *masked, *g1b, *tb;
    cudaGetSymbolAddress((void**)&masked, g_masked);
    cudaGetSymbolAddress((void**)&g1b, g_g1);
    cudaGetSymbolAddress((void**)&tb, g_t);

    init_kernel<<<1, 128>>>();

    dim3 gg(NPIX / 128, CT / 128);   // (256, 2)
    conv1x1_mask_kernel<<<gg, 256>>>(S, Wa, ba, masked);
    conv3x3_kernel<true ><<<gg, 256>>>(masked, W1, b1, g1b);
    conv3x3_kernel<false><<<gg, 256>>>(g1b, W2, b2, tb);

    dot_kernel<<<DTOT / 2048, 256>>>(T, tb);
    finalize_kernel<<<1, 1>>>(out);
}

// round 3
// speedup vs baseline: 2.1696x; 2.1696x over previous
#include <cuda_runtime.h>
#include <cuda_bf16.h>
#include <cstdint>
#include <math.h>

#define NIMG 8
#define CS   128
#define CT   256
#define PIX  4096           // 64*64
#define DTOT (CT*PIX)       // per image

// ---- scratch (__device__ globals; no allocation allowed) ----
__device__ float g_masked[(size_t)NIMG*CT*PIX];
__device__ float g_g1[(size_t)NIMG*CT*PIX];
__device__ float g_t[(size_t)NIMG*CT*PIX];
__device__ double g_acc[72];

__device__ __nv_bfloat16 g_WaHi[256*128], g_WaLo[256*128];
__device__ __nv_bfloat16 g_W1Hi[9*256*256], g_W1Lo[9*256*256];
__device__ __nv_bfloat16 g_W2Hi[9*256*256], g_W2Lo[9*256*256];

// =====================================================================
// warp-MMA helpers (sm_80+ baseline PTX: compiles for base sm_103)
// =====================================================================
__device__ __forceinline__ uint32_t smem_u32(const void* p) {
    uint32_t a;
    asm("{ .reg .u64 t; cvta.to.shared.u64 t, %1; cvt.u32.u64 %0, t; }" : "=r"(a) : "l"(p));
    return a;
}
__device__ __forceinline__ void ldsm4(uint32_t* r, uint32_t addr) {
    asm volatile("ldmatrix.sync.aligned.m8n8.x4.shared.b16 {%0,%1,%2,%3}, [%4];"
                 : "=r"(r[0]), "=r"(r[1]), "=r"(r[2]), "=r"(r[3]) : "r"(addr));
}
__device__ __forceinline__ void mma16816(float* c, const uint32_t* a, uint32_t b0, uint32_t b1) {
    asm volatile("mma.sync.aligned.m16n8k16.row.col.f32.bf16.bf16.f32 "
                 "{%0,%1,%2,%3}, {%4,%5,%6,%7}, {%8,%9}, {%0,%1,%2,%3};"
                 : "+f"(c[0]), "+f"(c[1]), "+f"(c[2]), "+f"(c[3])
                 : "r"(a[0]), "r"(a[1]), "r"(a[2]), "r"(a[3]), "r"(b0), "r"(b1));
}

// =====================================================================
// Weight pre-transform: fp32 -> bf16 hi/lo, tap-major for 3x3
// =====================================================================
__global__ void wprep_kernel(const float* __restrict__ Wa, const float* __restrict__ W1,
                             const float* __restrict__ W2) {
    int t = blockIdx.x * blockDim.x + threadIdx.x;
    if (t < 256*128) {
        float v = Wa[t];
        __nv_bfloat16 h = __float2bfloat16(v);
        g_WaHi[t] = h;
        g_WaLo[t] = __float2bfloat16(v - __bfloat162float(h));
    }
    int u = t - 256*128;
    if (u >= 0 && u < 9*256*256) {
        int r = u / 65536;
        int rem = u & 65535;
        int co = rem >> 8, ci = rem & 255;
        int src = (co*256 + ci)*9 + r;
        float v1 = W1[src];
        __nv_bfloat16 h1 = __float2bfloat16(v1);
        g_W1Hi[u] = h1;
        g_W1Lo[u] = __float2bfloat16(v1 - __bfloat162float(h1));
        float v2 = W2[src];
        __nv_bfloat16 h2 = __float2bfloat16(v2);
        g_W2Hi[u] = h2;
        g_W2Lo[u] = __float2bfloat16(v2 - __bfloat162float(h2));
    }
}

__global__ void init_kernel() {
    if (threadIdx.x < 72) g_acc[threadIdx.x] = 0.0;
}

// =====================================================================
// conv via warp mma.sync, bf16x3 emulated fp32.
// grid (256, 2): x = img*32 + pixtile, y = co-tile. 256 threads (8 warps).
// CTA tile 128co x 128pix, BK=32. SMEM stage 32KB: Ahi|Alo|Bhi|Blo,
// each tile stored [khalf(4)][row(128)][16B] -> ldmatrix conflict-free.
// Chunk order: channel-slab outer, taps inner (input slab stays L1-hot).
// =====================================================================
template<int TAPS, int CIN, bool RELU, bool MASK>
__global__ __launch_bounds__(256)
void conv_mma(const __nv_bfloat16* __restrict__ Whi, const __nv_bfloat16* __restrict__ Wlo,
              const float* __restrict__ bias, const float* __restrict__ in,
              float* __restrict__ out) {
    extern __shared__ char sm[];
    const int tid  = threadIdx.x;
    const int lane = tid & 31, wid = tid >> 5;
    const int m0   = blockIdx.y * 128;
    const int bx   = blockIdx.x;
    const int img  = bx >> 5;
    const int pix0 = (bx & 31) * 128;
    const int h0   = pix0 >> 6;
    const float* inImg = in + (size_t)img * CIN * PIX;

    constexpr int NCH = TAPS * (CIN / 32);

    // loader indices
    const int a_row = tid >> 1;
    const int a_k0  = (tid & 1) * 16;
    const int b_n   = tid & 127;
    const int b_sg  = tid >> 7;
    const int brow  = b_n >> 6;
    const int bw    = b_n & 63;

    uint4 rAh[2], rAl[2];
    float rB[16];

    auto ldg_chunk = [&](int it) {
        int tap, c0;
        if (TAPS == 1) { tap = 0; c0 = it * 32; }
        else           { tap = it % 9; c0 = (it / 9) * 32; }
        const int dh = (TAPS == 1) ? 0 : (tap / 3 - 1);
        const int dw = (TAPS == 1) ? 0 : (tap % 3 - 1);
        size_t aoff = (size_t)(tap * 256 + m0 + a_row) * CIN + c0 + a_k0;
        rAh[0] = *(const uint4*)(Whi + aoff);
        rAh[1] = *(const uint4*)(Whi + aoff + 8);
        rAl[0] = *(const uint4*)(Wlo + aoff);
        rAl[1] = *(const uint4*)(Wlo + aoff + 8);
        int h = h0 + brow + dh, w = bw + dw;
        bool ok = ((unsigned)h < 64u) & ((unsigned)w < 64u);
        const float* p = inImg + (size_t)(c0 + b_sg * 16) * PIX + h * 64 + w;
#pragma unroll
        for (int q = 0; q < 16; q++)
            rB[q] = ok ? __ldg(p + (size_t)q * PIX) : 0.f;
    };

    auto sts_chunk = [&](int s) {
        char* Ahi = sm + s * 32768;
        char* Alo = Ahi + 8192;
        char* Bhi = Ahi + 16384;
        char* Blo = Ahi + 24576;
        const int kh0 = a_k0 >> 3;      // 0 or 2
        *(uint4*)(Ahi + (kh0    ) * 2048 + a_row * 16) = rAh[0];
        *(uint4*)(Ahi + (kh0 + 1) * 2048 + a_row * 16) = rAh[1];
        *(uint4*)(Alo + (kh0    ) * 2048 + a_row * 16) = rAl[0];
        *(uint4*)(Alo + (kh0 + 1) * 2048 + a_row * 16) = rAl[1];
#pragma unroll
        for (int g = 0; g < 2; g++) {
            uint32_t hp[4], lp[4];
#pragma unroll
            for (int jp = 0; jp < 4; jp++) {
                float x0 = rB[g * 8 + 2 * jp], x1 = rB[g * 8 + 2 * jp + 1];
                __nv_bfloat16 hb0 = __float2bfloat16(x0);
                __nv_bfloat16 hb1 = __float2bfloat16(x1);
                __nv_bfloat16 lb0 = __float2bfloat16(x0 - __bfloat162float(hb0));
                __nv_bfloat16 lb1 = __float2bfloat16(x1 - __bfloat162float(hb1));
                hp[jp] = (uint32_t)__bfloat16_as_ushort(hb0)
                       | ((uint32_t)__bfloat16_as_ushort(hb1) << 16);
                lp[jp] = (uint32_t)__bfloat16_as_ushort(lb0)
                       | ((uint32_t)__bfloat16_as_ushort(lb1) << 16);
            }
            const int kh = b_sg * 2 + g;
            *(uint4*)(Bhi + kh * 2048 + b_n * 16) = make_uint4(hp[0], hp[1], hp[2], hp[3]);
            *(uint4*)(Blo + kh * 2048 + b_n * 16) = make_uint4(lp[0], lp[1], lp[2], lp[3]);
        }
    };

    float acc[4][4][4];
#pragma unroll
    for (int i = 0; i < 4; i++)
#pragma unroll
        for (int j = 0; j < 4; j++)
#pragma unroll
            for (int k = 0; k < 4; k++) acc[i][j][k] = 0.f;

    const int warp_m = wid & 1;   // 0/1 -> m offset 0/64
    const int warp_n = wid >> 1;  // 0..3 -> n offset *32
    const uint32_t smem0 = smem_u32(sm);

    ldg_chunk(0);
    sts_chunk(0);
    __syncthreads();

    for (int it = 0; it < NCH; ++it) {
        if (it + 1 < NCH) ldg_chunk(it + 1);

        const uint32_t S = smem0 + (it & 1) * 32768;
#pragma unroll
        for (int k16 = 0; k16 < 2; ++k16) {
            uint32_t ah[4][4], al[4][4], bh[2][4], bl[2][4];
            const int khl = k16 * 2 + (lane >> 4);
#pragma unroll
            for (int mt = 0; mt < 4; ++mt) {
                const int row = warp_m * 64 + mt * 16 + (lane & 7) + ((lane >> 3) & 1) * 8;
                const uint32_t ad = S + khl * 2048 + row * 16;
                ldsm4(ah[mt], ad);
                ldsm4(al[mt], ad + 8192);
            }
#pragma unroll
            for (int ng = 0; ng < 2; ++ng) {
                const int nrow = warp_n * 32 + ng * 16 + (lane & 7) + ((lane >> 3) & 1) * 8;
                const uint32_t bd = S + 16384 + khl * 2048 + nrow * 16;
                ldsm4(bh[ng], bd);
                ldsm4(bl[ng], bd + 8192);
            }
#pragma unroll
            for (int mt = 0; mt < 4; ++mt)
#pragma unroll
                for (int nt = 0; nt < 4; ++nt) {
                    const uint32_t b0h = bh[nt >> 1][nt & 1], b1h = bh[nt >> 1][2 + (nt & 1)];
                    const uint32_t b0l = bl[nt >> 1][nt & 1], b1l = bl[nt >> 1][2 + (nt & 1)];
                    mma16816(acc[mt][nt], ah[mt], b0h, b1h);
                    mma16816(acc[mt][nt], ah[mt], b0l, b1l);
                    mma16816(acc[mt][nt], al[mt], b0h, b1h);
                }
        }

        if (it + 1 < NCH) sts_chunk((it + 1) & 1);
        __syncthreads();
    }

    // epilogue
    const int l4 = lane >> 2, l2 = lane & 3;
    float* outImg = out + (size_t)img * CT * PIX;
#pragma unroll
    for (int mt = 0; mt < 4; ++mt) {
        const int co0 = m0 + warp_m * 64 + mt * 16 + l4;
        const float bi0 = bias[co0], bi1 = bias[co0 + 8];
#pragma unroll
        for (int nt = 0; nt < 4; ++nt) {
            const int p = pix0 + warp_n * 32 + nt * 8 + l2 * 2;
            float v0 = acc[mt][nt][0] + bi0;
            float v1 = acc[mt][nt][1] + bi0;
            float v2 = acc[mt][nt][2] + bi1;
            float v3 = acc[mt][nt][3] + bi1;
            if (RELU) {
                v0 = fmaxf(v0, 0.f); v1 = fmaxf(v1, 0.f);
                v2 = fmaxf(v2, 0.f); v3 = fmaxf(v3, 0.f);
            }
            if (MASK) {
                const int par0 = ((p >> 6) + (p & 63)) & 1;  // keep where parity==1
                if (par0) { v1 = 0.f; v3 = 0.f; }
                else      { v0 = 0.f; v2 = 0.f; }
            }
            *(float2*)(outImg + (size_t)co0 * PIX + p)       = make_float2(v0, v1);
            *(float2*)(outImg + (size_t)(co0 + 8) * PIX + p) = make_float2(v2, v3);
        }
    }
}

// =====================================================================
// pairwise dots + target norms (unchanged, verified)
// =====================================================================
__global__ __launch_bounds__(256)
void dot_kernel(const float* __restrict__ p, const float* __restrict__ t) {
    const int tid = threadIdx.x;
    const int d0  = blockIdx.x * 2048 + tid;

    float dacc[8][8];
    float tn[8];
#pragma unroll
    for (int i = 0; i < 8; i++) {
        tn[i] = 0.f;
#pragma unroll
        for (int j = 0; j < 8; j++) dacc[i][j] = 0.f;
    }
#pragma unroll 2
    for (int it = 0; it < 8; it++) {
        int d = d0 + it * 256;
        float pv[8], tv[8];
#pragma unroll
        for (int i = 0; i < 8; i++) {
            pv[i] = __ldg(p + (size_t)i * DTOT + d);
            tv[i] = __ldg(t + (size_t)i * DTOT + d);
        }
#pragma unroll
        for (int j = 0; j < 8; j++) tn[j] = fmaf(tv[j], tv[j], tn[j]);
#pragma unroll
        for (int i = 0; i < 8; i++)
#pragma unroll
            for (int j = 0; j < 8; j++)
                dacc[i][j] = fmaf(pv[i], tv[j], dacc[i][j]);
    }
    __shared__ float red[8][72];
    const int lane = tid & 31, warp = tid >> 5;
#pragma unroll
    for (int i = 0; i < 8; i++)
#pragma unroll
        for (int j = 0; j < 8; j++) {
            float v = dacc[i][j];
#pragma unroll
            for (int s = 16; s; s >>= 1) v += __shfl_xor_sync(0xFFFFFFFFu, v, s);
            if (lane == 0) red[warp][i*8+j] = v;
        }
#pragma unroll
    for (int j = 0; j < 8; j++) {
        float v = tn[j];
#pragma unroll
        for (int s = 16; s; s >>= 1) v += __shfl_xor_sync(0xFFFFFFFFu, v, s);
        if (lane == 0) red[warp][64+j] = v;
    }
    __syncthreads();
    if (tid < 72) {
        double s = 0.0;
#pragma unroll
        for (int w = 0; w < 8; w++) s += (double)red[w][tid];
        atomicAdd(&g_acc[tid], s);
    }
}

__global__ void finalize_kernel(float* __restrict__ out) {
    if (threadIdx.x != 0 || blockIdx.x != 0) return;
    double L[8][8];
    for (int i = 0; i < 8; i++)
        for (int j = 0; j < 8; j++)
            L[i][j] = (g_acc[i*8+j] - 0.5 * g_acc[64+j]) / 64.0;
    double ce = 0.0;
    for (int i = 0; i < 8; i++) {
        double m = L[i][0];
        for (int j = 1; j < 8; j++) m = L[i][j] > m ? L[i][j] : m;
        double s = 0.0;
        for (int j = 0; j < 8; j++) s += exp(L[i][j] - m);
        ce += (m + log(s)) - L[i][i];
    }
    ce /= 8.0;
    double loss = ce * (2.0 * 64.0 / 8.0) * 2e-05;
    out[0] = (float)loss;
}

// =====================================================================
extern "C" void kernel_launch(void* const* d_in, const int* in_sizes, int n_in,
                              void* d_out, int out_size) {
    const float* S  = (const float*)d_in[0];
    const float* T  = (const float*)d_in[1];
    const float* Wa = (const float*)d_in[2];
    const float* ba = (const float*)d_in[3];
    const float* W1 = (const float*)d_in[4];
    const float* b1 = (const float*)d_in[5];
    const float* W2 = (const float*)d_in[6];
    const float* b2 = (const float*)d_in[7];
    float* out = (float*)d_out;

    float *masked, *g1b, *tbuf;
    cudaGetSymbolAddress((void**)&masked, g_masked);
    cudaGetSymbolAddress((void**)&g1b, g_g1);
    cudaGetSymbolAddress((void**)&tbuf, g_t);
    __nv_bfloat16 *waH, *waL, *w1H, *w1L, *w2H, *w2L;
    cudaGetSymbolAddress((void**)&waH, g_WaHi);
    cudaGetSymbolAddress((void**)&waL, g_WaLo);
    cudaGetSymbolAddress((void**)&w1H, g_W1Hi);
    cudaGetSymbolAddress((void**)&w1L, g_W1Lo);
    cudaGetSymbolAddress((void**)&w2H, g_W2Hi);
    cudaGetSymbolAddress((void**)&w2L, g_W2Lo);

    const int SMEM = 65536;  // 2 stages * 32KB
    cudaFuncSetAttribute(conv_mma<1, 128, false, true >, cudaFuncAttributeMaxDynamicSharedMemorySize, SMEM);
    cudaFuncSetAttribute(conv_mma<9, 256, true,  false>, cudaFuncAttributeMaxDynamicSharedMemorySize, SMEM);
    cudaFuncSetAttribute(conv_mma<9, 256, false, false>, cudaFuncAttributeMaxDynamicSharedMemorySize, SMEM);

    init_kernel<<<1, 128>>>();
    {
        int total = 256*128 + 9*256*256;
        wprep_kernel<<<(total + 255) / 256, 256>>>(Wa, W1, W2);
    }
    dim3 gg(256, 2);
    conv_mma<1, 128, false, true ><<<gg, 256, SMEM>>>(waH, waL, ba, S,      masked);
    conv_mma<9, 256, true,  false><<<gg, 256, SMEM>>>(w1H, w1L, b1, masked, g1b);
    conv_mma<9, 256, false, false><<<gg, 256, SMEM>>>(w2H, w2L, b2, g1b,    tbuf);

    dot_kernel<<<DTOT / 2048, 256>>>(T, tbuf);
    finalize_kernel<<<1, 1>>>(out);
}

// round 4
// speedup vs baseline: 2.3792x; 1.0966x over previous
#include <cuda_runtime.h>
#include <cuda_bf16.h>
#include <cstdint>
#include <math.h>

#define NIMG 8
#define CS   128
#define CT   256
#define PIX  4096           // 64*64
#define DTOT (CT*PIX)       // per image

// ---- scratch (__device__ globals; no allocation allowed) ----
__device__ float g_masked[(size_t)NIMG*CT*PIX];
__device__ float g_g1[(size_t)NIMG*CT*PIX];
__device__ float g_t[(size_t)NIMG*CT*PIX];
__device__ double g_acc[72];

__device__ __nv_bfloat16 g_WaHi[256*128], g_WaLo[256*128];
__device__ __nv_bfloat16 g_W1Hi[9*256*256], g_W1Lo[9*256*256];
__device__ __nv_bfloat16 g_W2Hi[9*256*256], g_W2Lo[9*256*256];

// =====================================================================
// warp-MMA helpers (sm_80+ baseline PTX: compiles for base sm_103)
// =====================================================================
__device__ __forceinline__ uint32_t smem_u32(const void* p) {
    uint32_t a;
    asm("{ .reg .u64 t; cvta.to.shared.u64 t, %1; cvt.u32.u64 %0, t; }" : "=r"(a) : "l"(p));
    return a;
}
__device__ __forceinline__ void ldsm4(uint32_t* r, uint32_t addr) {
    asm volatile("ldmatrix.sync.aligned.m8n8.x4.shared.b16 {%0,%1,%2,%3}, [%4];"
                 : "=r"(r[0]), "=r"(r[1]), "=r"(r[2]), "=r"(r[3]) : "r"(addr));
}
__device__ __forceinline__ void mma16816(float* c, const uint32_t* a, uint32_t b0, uint32_t b1) {
    asm volatile("mma.sync.aligned.m16n8k16.row.col.f32.bf16.bf16.f32 "
                 "{%0,%1,%2,%3}, {%4,%5,%6,%7}, {%8,%9}, {%0,%1,%2,%3};"
                 : "+f"(c[0]), "+f"(c[1]), "+f"(c[2]), "+f"(c[3])
                 : "r"(a[0]), "r"(a[1]), "r"(a[2]), "r"(a[3]), "r"(b0), "r"(b1));
}

// =====================================================================
// Weight pre-transform: fp32 -> bf16 hi/lo, tap-major for 3x3
// =====================================================================
__global__ void wprep_kernel(const float* __restrict__ Wa, const float* __restrict__ W1,
                             const float* __restrict__ W2) {
    int t = blockIdx.x * blockDim.x + threadIdx.x;
    if (t < 256*128) {
        float v = Wa[t];
        __nv_bfloat16 h = __float2bfloat16(v);
        g_WaHi[t] = h;
        g_WaLo[t] = __float2bfloat16(v - __bfloat162float(h));
    }
    int u = t - 256*128;
    if (u >= 0 && u < 9*256*256) {
        int r = u / 65536;
        int rem = u & 65535;
        int co = rem >> 8, ci = rem & 255;
        int src = (co*256 + ci)*9 + r;
        float v1 = W1[src];
        __nv_bfloat16 h1 = __float2bfloat16(v1);
        g_W1Hi[u] = h1;
        g_W1Lo[u] = __float2bfloat16(v1 - __bfloat162float(h1));
        float v2 = W2[src];
        __nv_bfloat16 h2 = __float2bfloat16(v2);
        g_W2Hi[u] = h2;
        g_W2Lo[u] = __float2bfloat16(v2 - __bfloat162float(h2));
    }
}

__global__ void init_kernel() {
    if (threadIdx.x < 72) g_acc[threadIdx.x] = 0.0;
}

// =====================================================================
// conv via warp mma.sync, bf16x3 emulated fp32.
// grid (256, 2): x = img*32 + pixtile, y = co-tile. 256 threads (8 warps),
// 2 CTAs/SM (launch_bounds caps regs at 128; frag loads restructured so
// live set ~100 regs -> no spills).
// CTA tile 128co x 128pix, BK=32. SMEM stage 32KB: Ahi|Alo|Bhi|Blo,
// each tile stored [khalf(4)][row(128)][16B] -> ldmatrix conflict-free.
// =====================================================================
template<int TAPS, int CIN, bool RELU, bool MASK>
__global__ __launch_bounds__(256, 2)
void conv_mma(const __nv_bfloat16* __restrict__ Whi, const __nv_bfloat16* __restrict__ Wlo,
              const float* __restrict__ bias, const float* __restrict__ in,
              float* __restrict__ out) {
    extern __shared__ char sm[];
    const int tid  = threadIdx.x;
    const int lane = tid & 31, wid = tid >> 5;
    const int m0   = blockIdx.y * 128;
    const int bx   = blockIdx.x;
    const int img  = bx >> 5;
    const int pix0 = (bx & 31) * 128;
    const int h0   = pix0 >> 6;
    const float* inImg = in + (size_t)img * CIN * PIX;

    constexpr int NCH = TAPS * (CIN / 32);

    // loader indices
    const int a_row = tid >> 1;
    const int a_k0  = (tid & 1) * 16;
    const int b_n   = tid & 127;
    const int b_sg  = tid >> 7;
    const int brow  = b_n >> 6;
    const int bw    = b_n & 63;

    uint4 rAh[2], rAl[2];
    float rB[16];

    auto ldg_chunk = [&](int it) {
        int tap, c0;
        if (TAPS == 1) { tap = 0; c0 = it * 32; }
        else           { tap = it % 9; c0 = (it / 9) * 32; }
        const int dh = (TAPS == 1) ? 0 : (tap / 3 - 1);
        const int dw = (TAPS == 1) ? 0 : (tap % 3 - 1);
        size_t aoff = (size_t)(tap * 256 + m0 + a_row) * CIN + c0 + a_k0;
        rAh[0] = *(const uint4*)(Whi + aoff);
        rAh[1] = *(const uint4*)(Whi + aoff + 8);
        rAl[0] = *(const uint4*)(Wlo + aoff);
        rAl[1] = *(const uint4*)(Wlo + aoff + 8);
        int h = h0 + brow + dh, w = bw + dw;
        bool ok = ((unsigned)h < 64u) & ((unsigned)w < 64u);
        const float* p = inImg + (size_t)(c0 + b_sg * 16) * PIX + h * 64 + w;
#pragma unroll
        for (int q = 0; q < 16; q++)
            rB[q] = ok ? __ldg(p + (size_t)q * PIX) : 0.f;
    };

    auto sts_chunk = [&](int s) {
        char* Ahi = sm + s * 32768;
        char* Alo = Ahi + 8192;
        char* Bhi = Ahi + 16384;
        char* Blo = Ahi + 24576;
        const int kh0 = a_k0 >> 3;      // 0 or 2
        *(uint4*)(Ahi + (kh0    ) * 2048 + a_row * 16) = rAh[0];
        *(uint4*)(Ahi + (kh0 + 1) * 2048 + a_row * 16) = rAh[1];
        *(uint4*)(Alo + (kh0    ) * 2048 + a_row * 16) = rAl[0];
        *(uint4*)(Alo + (kh0 + 1) * 2048 + a_row * 16) = rAl[1];
#pragma unroll
        for (int g = 0; g < 2; g++) {
            uint32_t hp[4], lp[4];
#pragma unroll
            for (int jp = 0; jp < 4; jp++) {
                float x0 = rB[g * 8 + 2 * jp], x1 = rB[g * 8 + 2 * jp + 1];
                __nv_bfloat16 hb0 = __float2bfloat16(x0);
                __nv_bfloat16 hb1 = __float2bfloat16(x1);
                __nv_bfloat16 lb0 = __float2bfloat16(x0 - __bfloat162float(hb0));
                __nv_bfloat16 lb1 = __float2bfloat16(x1 - __bfloat162float(hb1));
                hp[jp] = (uint32_t)__bfloat16_as_ushort(hb0)
                       | ((uint32_t)__bfloat16_as_ushort(hb1) << 16);
                lp[jp] = (uint32_t)__bfloat16_as_ushort(lb0)
                       | ((uint32_t)__bfloat16_as_ushort(lb1) << 16);
            }
            const int kh = b_sg * 2 + g;
            *(uint4*)(Bhi + kh * 2048 + b_n * 16) = make_uint4(hp[0], hp[1], hp[2], hp[3]);
            *(uint4*)(Blo + kh * 2048 + b_n * 16) = make_uint4(lp[0], lp[1], lp[2], lp[3]);
        }
    };

    float acc[4][4][4];
#pragma unroll
    for (int i = 0; i < 4; i++)
#pragma unroll
        for (int j = 0; j < 4; j++)
#pragma unroll
            for (int k = 0; k < 4; k++) acc[i][j][k] = 0.f;

    const int warp_m = wid & 1;   // 0/1 -> m offset 0/64
    const int warp_n = wid >> 1;  // 0..3 -> n offset *32
    const uint32_t smem0 = smem_u32(sm);
    // per-lane ldmatrix row selectors (hoisted)
    const int lrow = (lane & 7) + ((lane >> 3) & 1) * 8;
    const int lkh  = (lane >> 4);   // 0/1: which khalf within k16

    ldg_chunk(0);
    sts_chunk(0);
    __syncthreads();

    for (int it = 0; it < NCH; ++it) {
        if (it + 1 < NCH) ldg_chunk(it + 1);

        const uint32_t S = smem0 + (it & 1) * 32768;
#pragma unroll
        for (int k16 = 0; k16 < 2; ++k16) {
            const int khl = k16 * 2 + lkh;
            const uint32_t kbase = S + khl * 2048;

            // B fragments first (16 regs live)
            uint32_t bh[2][4], bl[2][4];
#pragma unroll
            for (int ng = 0; ng < 2; ++ng) {
                const uint32_t bd = kbase + 16384 + (warp_n * 32 + ng * 16 + lrow) * 16;
                ldsm4(bh[ng], bd);
                ldsm4(bl[ng], bd + 8192);
            }
            // A fragments per m-tile (8 regs live at a time)
#pragma unroll
            for (int mt = 0; mt < 4; ++mt) {
                uint32_t ah[4], al[4];
                const uint32_t ad = kbase + (warp_m * 64 + mt * 16 + lrow) * 16;
                ldsm4(ah, ad);
                ldsm4(al, ad + 8192);
#pragma unroll
                for (int nt = 0; nt < 4; ++nt) {
                    const uint32_t b0h = bh[nt >> 1][nt & 1], b1h = bh[nt >> 1][2 + (nt & 1)];
                    const uint32_t b0l = bl[nt >> 1][nt & 1], b1l = bl[nt >> 1][2 + (nt & 1)];
                    mma16816(acc[mt][nt], ah, b0h, b1h);
                    mma16816(acc[mt][nt], ah, b0l, b1l);
                    mma16816(acc[mt][nt], al, b0h, b1h);
                }
            }
        }

        if (it + 1 < NCH) sts_chunk((it + 1) & 1);
        __syncthreads();
    }

    // epilogue
    const int l4 = lane >> 2, l2 = lane & 3;
    float* outImg = out + (size_t)img * CT * PIX;
#pragma unroll
    for (int mt = 0; mt < 4; ++mt) {
        const int co0 = m0 + warp_m * 64 + mt * 16 + l4;
        const float bi0 = bias[co0], bi1 = bias[co0 + 8];
#pragma unroll
        for (int nt = 0; nt < 4; ++nt) {
            const int p = pix0 + warp_n * 32 + nt * 8 + l2 * 2;
            float v0 = acc[mt][nt][0] + bi0;
            float v1 = acc[mt][nt][1] + bi0;
            float v2 = acc[mt][nt][2] + bi1;
            float v3 = acc[mt][nt][3] + bi1;
            if (RELU) {
                v0 = fmaxf(v0, 0.f); v1 = fmaxf(v1, 0.f);
                v2 = fmaxf(v2, 0.f); v3 = fmaxf(v3, 0.f);
            }
            if (MASK) {
                const int par0 = ((p >> 6) + (p & 63)) & 1;  // keep where parity==1
                if (par0) { v1 = 0.f; v3 = 0.f; }
                else      { v0 = 0.f; v2 = 0.f; }
            }
            *(float2*)(outImg + (size_t)co0 * PIX + p)       = make_float2(v0, v1);
            *(float2*)(outImg + (size_t)(co0 + 8) * PIX + p) = make_float2(v2, v3);
        }
    }
}

// =====================================================================
// pairwise dots + target norms (unchanged, verified)
// =====================================================================
__global__ __launch_bounds__(256)
void dot_kernel(const float* __restrict__ p, const float* __restrict__ t) {
    const int tid = threadIdx.x;
    const int d0  = blockIdx.x * 2048 + tid;

    float dacc[8][8];
    float tn[8];
#pragma unroll
    for (int i = 0; i < 8; i++) {
        tn[i] = 0.f;
#pragma unroll
        for (int j = 0; j < 8; j++) dacc[i][j] = 0.f;
    }
#pragma unroll 2
    for (int it = 0; it < 8; it++) {
        int d = d0 + it * 256;
        float pv[8], tv[8];
#pragma unroll
        for (int i = 0; i < 8; i++) {
            pv[i] = __ldg(p + (size_t)i * DTOT + d);
            tv[i] = __ldg(t + (size_t)i * DTOT + d);
        }
#pragma unroll
        for (int j = 0; j < 8; j++) tn[j] = fmaf(tv[j], tv[j], tn[j]);
#pragma unroll
        for (int i = 0; i < 8; i++)
#pragma unroll
            for (int j = 0; j < 8; j++)
                dacc[i][j] = fmaf(pv[i], tv[j], dacc[i][j]);
    }
    __shared__ float red[8][72];
    const int lane = tid & 31, warp = tid >> 5;
#pragma unroll
    for (int i = 0; i < 8; i++)
#pragma unroll
        for (int j = 0; j < 8; j++) {
            float v = dacc[i][j];
#pragma unroll
            for (int s = 16; s; s >>= 1) v += __shfl_xor_sync(0xFFFFFFFFu, v, s);
            if (lane == 0) red[warp][i*8+j] = v;
        }
#pragma unroll
    for (int j = 0; j < 8; j++) {
        float v = tn[j];
#pragma unroll
        for (int s = 16; s; s >>= 1) v += __shfl_xor_sync(0xFFFFFFFFu, v, s);
        if (lane == 0) red[warp][64+j] = v;
    }
    __syncthreads();
    if (tid < 72) {
        double s = 0.0;
#pragma unroll
        for (int w = 0; w < 8; w++) s += (double)red[w][tid];
        atomicAdd(&g_acc[tid], s);
    }
}

__global__ void finalize_kernel(float* __restrict__ out) {
    if (threadIdx.x != 0 || blockIdx.x != 0) return;
    double L[8][8];
    for (int i = 0; i < 8; i++)
        for (int j = 0; j < 8; j++)
            L[i][j] = (g_acc[i*8+j] - 0.5 * g_acc[64+j]) / 64.0;
    double ce = 0.0;
    for (int i = 0; i < 8; i++) {
        double m = L[i][0];
        for (int j = 1; j < 8; j++) m = L[i][j] > m ? L[i][j] : m;
        double s = 0.0;
        for (int j = 0; j < 8; j++) s += exp(L[i][j] - m);
        ce += (m + log(s)) - L[i][i];
    }
    ce /= 8.0;
    double loss = ce * (2.0 * 64.0 / 8.0) * 2e-05;
    out[0] = (float)loss;
}

// =====================================================================
extern "C" void kernel_launch(void* const* d_in, const int* in_sizes, int n_in,
                              void* d_out, int out_size) {
    const float* S  = (const float*)d_in[0];
    const float* T  = (const float*)d_in[1];
    const float* Wa = (const float*)d_in[2];
    const float* ba = (const float*)d_in[3];
    const float* W1 = (const float*)d_in[4];
    const float* b1 = (const float*)d_in[5];
    const float* W2 = (const float*)d_in[6];
    const float* b2 = (const float*)d_in[7];
    float* out = (float*)d_out;

    float *masked, *g1b, *tbuf;
    cudaGetSymbolAddress((void**)&masked, g_masked);
    cudaGetSymbolAddress((void**)&g1b, g_g1);
    cudaGetSymbolAddress((void**)&tbuf, g_t);
    __nv_bfloat16 *waH, *waL, *w1H, *w1L, *w2H, *w2L;
    cudaGetSymbolAddress((void**)&waH, g_WaHi);
    cudaGetSymbolAddress((void**)&waL, g_WaLo);
    cudaGetSymbolAddress((void**)&w1H, g_W1Hi);
    cudaGetSymbolAddress((void**)&w1L, g_W1Lo);
    cudaGetSymbolAddress((void**)&w2H, g_W2Hi);
    cudaGetSymbolAddress((void**)&w2L, g_W2Lo);

    const int SMEM = 65536;  // 2 stages * 32KB
    cudaFuncSetAttribute(conv_mma<1, 128, false, true >, cudaFuncAttributeMaxDynamicSharedMemorySize, SMEM);
    cudaFuncSetAttribute(conv_mma<9, 256, true,  false>, cudaFuncAttributeMaxDynamicSharedMemorySize, SMEM);
    cudaFuncSetAttribute(conv_mma<9, 256, false, false>, cudaFuncAttributeMaxDynamicSharedMemorySize, SMEM);

    init_kernel<<<1, 128>>>();
    {
        int total = 256*128 + 9*256*256;
        wprep_kernel<<<(total + 255) / 256, 256>>>(Wa, W1, W2);
    }
    dim3 gg(256, 2);
    conv_mma<1, 128, false, true ><<<gg, 256, SMEM>>>(waH, waL, ba, S,      masked);
    conv_mma<9, 256, true,  false><<<gg, 256, SMEM>>>(w1H, w1L, b1, masked, g1b);
    conv_mma<9, 256, false, false><<<gg, 256, SMEM>>>(w2H, w2L, b2, g1b,    tbuf);

    dot_kernel<<<DTOT / 2048, 256>>>(T, tbuf);
    finalize_kernel<<<1, 1>>>(out);
}

// round 6
// speedup vs baseline: 2.4809x; 1.0428x over previous
#include <cuda_runtime.h>
#include <cuda_bf16.h>
#include <cstdint>
#include <math.h>

#define NIMG 8
#define CS   128
#define CT   256
#define PIX  4096           // 64*64
#define DTOT (CT*PIX)       // per image

// ---- scratch (__device__ globals; no allocation allowed) ----
__device__ float g_t[(size_t)NIMG*CT*PIX];
__device__ double g_acc[72];

// activations, split bf16 hi/lo, layout [img][kc(8)][pix(4096)][32ch]
__device__ __align__(16) __nv_bfloat16 g_mHi[(size_t)NIMG*8*4096*32];
__device__ __align__(16) __nv_bfloat16 g_mLo[(size_t)NIMG*8*4096*32];
__device__ __align__(16) __nv_bfloat16 g_g1Hi[(size_t)NIMG*8*4096*32];
__device__ __align__(16) __nv_bfloat16 g_g1Lo[(size_t)NIMG*8*4096*32];

// conv1 weights (old row-major hi/lo)
__device__ __align__(16) __nv_bfloat16 g_WaHi[256*128], g_WaLo[256*128];
// conv2/3 weights packed in SMEM-tile order:
// chunk = (tap*8+kc)*2+mb ; within 8192 elems: r(0..1023)*8+j
// r: hilo=r>>9, khalf=(r>>7)&3, co=r&127
__device__ __align__(16) __nv_bfloat16 g_W1p[9*8*2*8192];
__device__ __align__(16) __nv_bfloat16 g_W2p[9*8*2*8192];

// =====================================================================
// helpers (sm_80+ baseline PTX)
// =====================================================================
__device__ __forceinline__ uint32_t smem_u32(const void* p) {
    uint32_t a;
    asm("{ .reg .u64 t; cvta.to.shared.u64 t, %1; cvt.u32.u64 %0, t; }" : "=r"(a) : "l"(p));
    return a;
}
__device__ __forceinline__ void ldsm4(uint32_t* r, uint32_t addr) {
    asm volatile("ldmatrix.sync.aligned.m8n8.x4.shared.b16 {%0,%1,%2,%3}, [%4];"
                 : "=r"(r[0]), "=r"(r[1]), "=r"(r[2]), "=r"(r[3]) : "r"(addr));
}
__device__ __forceinline__ void mma16816(float* c, const uint32_t* a, uint32_t b0, uint32_t b1) {
    asm volatile("mma.sync.aligned.m16n8k16.row.col.f32.bf16.bf16.f32 "
                 "{%0,%1,%2,%3}, {%4,%5,%6,%7}, {%8,%9}, {%0,%1,%2,%3};"
                 : "+f"(c[0]), "+f"(c[1]), "+f"(c[2]), "+f"(c[3])
                 : "r"(a[0]), "r"(a[1]), "r"(a[2]), "r"(a[3]), "r"(b0), "r"(b1));
}
__device__ __forceinline__ void cp16(uint32_t dst, const void* src, uint32_t sz) {
    asm volatile("cp.async.cg.shared.global [%0], [%1], 16, %2;"
                 :: "r"(dst), "l"(src), "r"(sz) : "memory");
}
__device__ __forceinline__ void cp_commit() {
    asm volatile("cp.async.commit_group;" ::: "memory");
}
__device__ __forceinline__ void cp_wait1() {
    asm volatile("cp.async.wait_group 1;" ::: "memory");
}
__device__ __forceinline__ void bf16split(float v, __nv_bfloat16& h, __nv_bfloat16& l) {
    h = __float2bfloat16(v);
    l = __float2bfloat16(v - __bfloat162float(h));
}

// =====================================================================
// Weight prep
// =====================================================================
__global__ void wprep_kernel(const float* __restrict__ Wa, const float* __restrict__ W1,
                             const float* __restrict__ W2) {
    int t = blockIdx.x * blockDim.x + threadIdx.x;
    if (t < 256*128) {
        float v = Wa[t];
        __nv_bfloat16 h, l;
        bf16split(v, h, l);
        g_WaHi[t] = h; g_WaLo[t] = l;
    }
    int u = t - 256*128;
    if (u >= 0 && u < 9*8*2*8192) {
        int chunk  = u >> 13;
        int within = u & 8191;
        int r = within >> 3, j = within & 7;
        int tap = chunk >> 4;
        int kc  = (chunk >> 1) & 7;
        int mb  = chunk & 1;
        int hilo  = r >> 9;
        int khalf = (r >> 7) & 3;
        int co    = r & 127;
        int co_g  = mb * 128 + co;
        int ci    = kc * 32 + khalf * 8 + j;
        int src   = co_g * 2304 + ci * 9 + tap;
        {
            __nv_bfloat16 h, l;
            bf16split(W1[src], h, l);
            g_W1p[u] = hilo ? l : h;
        }
        {
            __nv_bfloat16 h, l;
            bf16split(W2[src], h, l);
            g_W2p[u] = hilo ? l : h;
        }
    }
}

__global__ void init_kernel() {
    if (threadIdx.x < 72) g_acc[threadIdx.x] = 0.0;
}

// =====================================================================
// conv1 (1x1, K=128): register-builder path, fp32 input, epilogue
// writes checkerboard-masked result as bf16 hi/lo planes [kc][pix][32].
// =====================================================================
__global__ __launch_bounds__(256, 2)
void conv1_mma(const __nv_bfloat16* __restrict__ Whi, const __nv_bfloat16* __restrict__ Wlo,
               const float* __restrict__ bias, const float* __restrict__ in,
               __nv_bfloat16* __restrict__ outHi, __nv_bfloat16* __restrict__ outLo) {
    extern __shared__ char sm[];
    const int tid  = threadIdx.x;
    const int lane = tid & 31, wid = tid >> 5;
    const int m0   = blockIdx.y * 128;
    const int bx   = blockIdx.x;
    const int img  = bx >> 5;
    const int pix0 = (bx & 31) * 128;
    const float* inImg = in + (size_t)img * CS * PIX;

    constexpr int NCH = CS / 32;  // 4

    const int a_row = tid >> 1;
    const int a_k0  = (tid & 1) * 16;
    const int b_n   = tid & 127;
    const int b_sg  = tid >> 7;

    uint4 rAh[2], rAl[2];
    float rB[16];

    auto ldg_chunk = [&](int it) {
        const int c0 = it * 32;
        size_t aoff = (size_t)(m0 + a_row) * CS + c0 + a_k0;
        rAh[0] = *(const uint4*)(Whi + aoff);
        rAh[1] = *(const uint4*)(Whi + aoff + 8);
        rAl[0] = *(const uint4*)(Wlo + aoff);
        rAl[1] = *(const uint4*)(Wlo + aoff + 8);
        const float* p = inImg + (size_t)(c0 + b_sg * 16) * PIX + pix0 + b_n;
#pragma unroll
        for (int q = 0; q < 16; q++)
            rB[q] = __ldg(p + (size_t)q * PIX);
    };

    auto sts_chunk = [&](int s) {
        char* Ahi = sm + s * 32768;
        char* Alo = Ahi + 8192;
        char* Bhi = Ahi + 16384;
        char* Blo = Ahi + 24576;
        const int kh0 = a_k0 >> 3;
        *(uint4*)(Ahi + (kh0    ) * 2048 + a_row * 16) = rAh[0];
        *(uint4*)(Ahi + (kh0 + 1) * 2048 + a_row * 16) = rAh[1];
        *(uint4*)(Alo + (kh0    ) * 2048 + a_row * 16) = rAl[0];
        *(uint4*)(Alo + (kh0 + 1) * 2048 + a_row * 16) = rAl[1];
#pragma unroll
        for (int g = 0; g < 2; g++) {
            uint32_t hp[4], lp[4];
#pragma unroll
            for (int jp = 0; jp < 4; jp++) {
                float x0 = rB[g * 8 + 2 * jp], x1 = rB[g * 8 + 2 * jp + 1];
                __nv_bfloat16 hb0, lb0, hb1, lb1;
                bf16split(x0, hb0, lb0);
                bf16split(x1, hb1, lb1);
                hp[jp] = (uint32_t)__bfloat16_as_ushort(hb0)
                       | ((uint32_t)__bfloat16_as_ushort(hb1) << 16);
                lp[jp] = (uint32_t)__bfloat16_as_ushort(lb0)
                       | ((uint32_t)__bfloat16_as_ushort(lb1) << 16);
            }
            const int kh = b_sg * 2 + g;
            *(uint4*)(Bhi + kh * 2048 + b_n * 16) = make_uint4(hp[0], hp[1], hp[2], hp[3]);
            *(uint4*)(Blo + kh * 2048 + b_n * 16) = make_uint4(lp[0], lp[1], lp[2], lp[3]);
        }
    };

    float acc[4][4][4];
#pragma unroll
    for (int i = 0; i < 4; i++)
#pragma unroll
        for (int j = 0; j < 4; j++)
#pragma unroll
            for (int k = 0; k < 4; k++) acc[i][j][k] = 0.f;

    const int warp_m = wid & 1;
    const int warp_n = wid >> 1;
    const uint32_t smem0 = smem_u32(sm);
    const int lrow = (lane & 7) + ((lane >> 3) & 1) * 8;
    const int lkh  = (lane >> 4);

    ldg_chunk(0);
    sts_chunk(0);
    __syncthreads();

    for (int it = 0; it < NCH; ++it) {
        if (it + 1 < NCH) ldg_chunk(it + 1);
        const uint32_t S = smem0 + (it & 1) * 32768;
#pragma unroll
        for (int k16 = 0; k16 < 2; ++k16) {
            const uint32_t kbase = S + (k16 * 2 + lkh) * 2048;
            uint32_t bh[2][4], bl[2][4];
#pragma unroll
            for (int ng = 0; ng < 2; ++ng) {
                const uint32_t bd = kbase + 16384 + (warp_n * 32 + ng * 16 + lrow) * 16;
                ldsm4(bh[ng], bd);
                ldsm4(bl[ng], bd + 8192);
            }
#pragma unroll
            for (int mt = 0; mt < 4; ++mt) {
                uint32_t ah[4], al[4];
                const uint32_t ad = kbase + (warp_m * 64 + mt * 16 + lrow) * 16;
                ldsm4(ah, ad);
                ldsm4(al, ad + 8192);
#pragma unroll
                for (int nt = 0; nt < 4; ++nt) {
                    const uint32_t b0h = bh[nt >> 1][nt & 1], b1h = bh[nt >> 1][2 + (nt & 1)];
                    const uint32_t b0l = bl[nt >> 1][nt & 1], b1l = bl[nt >> 1][2 + (nt & 1)];
                    mma16816(acc[mt][nt], ah, b0h, b1h);
                    mma16816(acc[mt][nt], ah, b0l, b1l);
                    mma16816(acc[mt][nt], al, b0h, b1h);
                }
            }
        }
        if (it + 1 < NCH) sts_chunk((it + 1) & 1);
        __syncthreads();
    }

    // epilogue: bias + checkerboard mask, split to hi/lo planes
    const int l4 = lane >> 2, l2 = lane & 3;
    const size_t imgbase = (size_t)img * 8 * 4096 * 32;
#pragma unroll
    for (int mt = 0; mt < 4; ++mt) {
        const int co0 = m0 + warp_m * 64 + mt * 16 + l4;
        const float bi0 = bias[co0], bi1 = bias[co0 + 8];
#pragma unroll
        for (int nt = 0; nt < 4; ++nt) {
            const int p = pix0 + warp_n * 32 + nt * 8 + l2 * 2;
            float v0 = acc[mt][nt][0] + bi0;
            float v1 = acc[mt][nt][1] + bi0;
            float v2 = acc[mt][nt][2] + bi1;
            float v3 = acc[mt][nt][3] + bi1;
            const int par0 = ((p >> 6) + (p & 63)) & 1;  // keep where parity==1
            if (par0) { v1 = 0.f; v3 = 0.f; }
            else      { v0 = 0.f; v2 = 0.f; }
            const size_t o00 = imgbase + ((size_t)(co0 >> 5) * 4096 + p) * 32 + (co0 & 31);
            const size_t o10 = imgbase + ((size_t)((co0 + 8) >> 5) * 4096 + p) * 32 + ((co0 + 8) & 31);
            __nv_bfloat16 h, l;
            bf16split(v0, h, l); outHi[o00]      = h; outLo[o00]      = l;
            bf16split(v1, h, l); outHi[o00 + 32] = h; outLo[o00 + 32] = l;
            bf16split(v2, h, l); outHi[o10]      = h; outLo[o10]      = l;
            bf16split(v3, h, l); outHi[o10 + 32] = h; outLo[o10 + 32] = l;
        }
    }
}

// =====================================================================
// conv3x3 via cp.async 3-stage pipeline. Zero builder math.
// A: packed weights (tile order). B: hi/lo activation planes with
// zero-fill for halo OOB. 72 chunks.
// B SMEM row layout (matches consumer): r = khalf*128 + pixel.
// =====================================================================
template<bool RELU, bool EPI_SPLIT>
__global__ __launch_bounds__(256, 2)
void conv_cp(const __nv_bfloat16* __restrict__ Wp,
             const float* __restrict__ bias,
             const __nv_bfloat16* __restrict__ actHi,
             const __nv_bfloat16* __restrict__ actLo,
             float* __restrict__ outF32,
             __nv_bfloat16* __restrict__ outHi,
             __nv_bfloat16* __restrict__ outLo) {
    extern __shared__ char sm[];
    const int tid  = threadIdx.x;
    const int lane = tid & 31, wid = tid >> 5;
    const int mb   = blockIdx.y;
    const int m0   = mb * 128;
    const int bx   = blockIdx.x;
    const int img  = bx >> 5;
    const int pix0 = (bx & 31) * 128;
    const int h0   = pix0 >> 6;

    constexpr int NCH = 72;
    const uint32_t smem0 = smem_u32(sm);

    // B-row constants: consumer layout r = khalf*128 + pixel  (FIX of R5 bug)
    const int r0 = tid, r1 = tid + 256;
    const int kh_r0 = r0 >> 7, px_r0 = r0 & 127;
    const int kh_r1 = r1 >> 7, px_r1 = r1 & 127;

    auto issue = [&](int it) {
        const int st = it % 3;
        const uint32_t stage = smem0 + st * 32768;
        const int tap = it % 9, kc = it / 9;
        const int dh = tap / 3 - 1, dw = tap % 3 - 1;
        // A: 4 coalesced 16B rows from packed weights
        const __nv_bfloat16* asrc = Wp + ((size_t)((tap * 8 + kc) * 2 + mb)) * 8192 + tid * 8;
#pragma unroll
        for (int i = 0; i < 4; i++)
            cp16(stage + (tid + 256 * i) * 16, asrc + 2048 * i, 16u);
        // B: 2 hi rows + 2 lo rows, zero-fill OOB
        const size_t actbase = ((size_t)(img * 8 + kc)) * 4096 * 32;
        {
            const int h = h0 + (px_r0 >> 6) + dh, w = (px_r0 & 63) + dw;
            const bool ok = ((unsigned)h < 64u) & ((unsigned)w < 64u);
            const size_t so = ok ? (actbase + (size_t)(h * 64 + w) * 32 + kh_r0 * 8) : 0;
            const uint32_t d = stage + 16384 + r0 * 16;
            cp16(d,        actHi + so, ok ? 16u : 0u);
            cp16(d + 8192, actLo + so, ok ? 16u : 0u);
        }
        {
            const int h = h0 + (px_r1 >> 6) + dh, w = (px_r1 & 63) + dw;
            const bool ok = ((unsigned)h < 64u) & ((unsigned)w < 64u);
            const size_t so = ok ? (actbase + (size_t)(h * 64 + w) * 32 + kh_r1 * 8) : 0;
            const uint32_t d = stage + 16384 + r1 * 16;
            cp16(d,        actHi + so, ok ? 16u : 0u);
            cp16(d + 8192, actLo + so, ok ? 16u : 0u);
        }
    };

    float acc[4][4][4];
#pragma unroll
    for (int i = 0; i < 4; i++)
#pragma unroll
        for (int j = 0; j < 4; j++)
#pragma unroll
            for (int k = 0; k < 4; k++) acc[i][j][k] = 0.f;

    const int warp_m = wid & 1;
    const int warp_n = wid >> 1;
    const int lrow = (lane & 7) + ((lane >> 3) & 1) * 8;
    const int lkh  = (lane >> 4);

    issue(0); cp_commit();
    issue(1); cp_commit();

    for (int it = 0; it < NCH; ++it) {
        cp_wait1();
        __syncthreads();
        if (it + 2 < NCH) issue(it + 2);
        cp_commit();

        const uint32_t S = smem0 + (it % 3) * 32768;
#pragma unroll
        for (int k16 = 0; k16 < 2; ++k16) {
            const uint32_t kbase = S + (k16 * 2 + lkh) * 2048;
            uint32_t bh[2][4], bl[2][4];
#pragma unroll
            for (int ng = 0; ng < 2; ++ng) {
                const uint32_t bd = kbase + 16384 + (warp_n * 32 + ng * 16 + lrow) * 16;
                ldsm4(bh[ng], bd);
                ldsm4(bl[ng], bd + 8192);
            }
#pragma unroll
            for (int mt = 0; mt < 4; ++mt) {
                uint32_t ah[4], al[4];
                const uint32_t ad = kbase + (warp_m * 64 + mt * 16 + lrow) * 16;
                ldsm4(ah, ad);
                ldsm4(al, ad + 8192);
#pragma unroll
                for (int nt = 0; nt < 4; ++nt) {
                    const uint32_t b0h = bh[nt >> 1][nt & 1], b1h = bh[nt >> 1][2 + (nt & 1)];
                    const uint32_t b0l = bl[nt >> 1][nt & 1], b1l = bl[nt >> 1][2 + (nt & 1)];
                    mma16816(acc[mt][nt], ah, b0h, b1h);
                    mma16816(acc[mt][nt], ah, b0l, b1l);
                    mma16816(acc[mt][nt], al, b0h, b1h);
                }
            }
        }
    }

    // epilogue
    const int l4 = lane >> 2, l2 = lane & 3;
#pragma unroll
    for (int mt = 0; mt < 4; ++mt) {
        const int co0 = m0 + warp_m * 64 + mt * 16 + l4;
        const float bi0 = bias[co0], bi1 = bias[co0 + 8];
#pragma unroll
        for (int nt = 0; nt < 4; ++nt) {
            const int p = pix0 + warp_n * 32 + nt * 8 + l2 * 2;
            float v0 = acc[mt][nt][0] + bi0;
            float v1 = acc[mt][nt][1] + bi0;
            float v2 = acc[mt][nt][2] + bi1;
            float v3 = acc[mt][nt][3] + bi1;
            if (RELU) {
                v0 = fmaxf(v0, 0.f); v1 = fmaxf(v1, 0.f);
                v2 = fmaxf(v2, 0.f); v3 = fmaxf(v3, 0.f);
            }
            if (EPI_SPLIT) {
                const size_t imgbase = (size_t)img * 8 * 4096 * 32;
                const size_t o00 = imgbase + ((size_t)(co0 >> 5) * 4096 + p) * 32 + (co0 & 31);
                const size_t o10 = imgbase + ((size_t)((co0 + 8) >> 5) * 4096 + p) * 32 + ((co0 + 8) & 31);
                __nv_bfloat16 h, l;
                bf16split(v0, h, l); outHi[o00]      = h; outLo[o00]      = l;
                bf16split(v1, h, l); outHi[o00 + 32] = h; outLo[o00 + 32] = l;
                bf16split(v2, h, l); outHi[o10]      = h; outLo[o10]      = l;
                bf16split(v3, h, l); outHi[o10 + 32] = h; outLo[o10 + 32] = l;
            } else {
                float* outImg = outF32 + (size_t)img * CT * PIX;
                *(float2*)(outImg + (size_t)co0 * PIX + p)       = make_float2(v0, v1);
                *(float2*)(outImg + (size_t)(co0 + 8) * PIX + p) = make_float2(v2, v3);
            }
        }
    }
}

// =====================================================================
// pairwise dots + target norms (unchanged, verified)
// =====================================================================
__global__ __launch_bounds__(256)
void dot_kernel(const float* __restrict__ p, const float* __restrict__ t) {
    const int tid = threadIdx.x;
    const int d0  = blockIdx.x * 2048 + tid;

    float dacc[8][8];
    float tn[8];
#pragma unroll
    for (int i = 0; i < 8; i++) {
        tn[i] = 0.f;
#pragma unroll
        for (int j = 0; j < 8; j++) dacc[i][j] = 0.f;
    }
#pragma unroll 2
    for (int it = 0; it < 8; it++) {
        int d = d0 + it * 256;
        float pv[8], tv[8];
#pragma unroll
        for (int i = 0; i < 8; i++) {
            pv[i] = __ldg(p + (size_t)i * DTOT + d);
            tv[i] = __ldg(t + (size_t)i * DTOT + d);
        }
#pragma unroll
        for (int j = 0; j < 8; j++) tn[j] = fmaf(tv[j], tv[j], tn[j]);
#pragma unroll
        for (int i = 0; i < 8; i++)
#pragma unroll
            for (int j = 0; j < 8; j++)
                dacc[i][j] = fmaf(pv[i], tv[j], dacc[i][j]);
    }
    __shared__ float red[8][72];
    const int lane = tid & 31, warp = tid >> 5;
#pragma unroll
    for (int i = 0; i < 8; i++)
#pragma unroll
        for (int j = 0; j < 8; j++) {
            float v = dacc[i][j];
#pragma unroll
            for (int s = 16; s; s >>= 1) v += __shfl_xor_sync(0xFFFFFFFFu, v, s);
            if (lane == 0) red[warp][i*8+j] = v;
        }
#pragma unroll
    for (int j = 0; j < 8; j++) {
        float v = tn[j];
#pragma unroll
        for (int s = 16; s; s >>= 1) v += __shfl_xor_sync(0xFFFFFFFFu, v, s);
        if (lane == 0) red[warp][64+j] = v;
    }
    __syncthreads();
    if (tid < 72) {
        double s = 0.0;
#pragma unroll
        for (int w = 0; w < 8; w++) s += (double)red[w][tid];
        atomicAdd(&g_acc[tid], s);
    }
}

__global__ void finalize_kernel(float* __restrict__ out) {
    if (threadIdx.x != 0 || blockIdx.x != 0) return;
    double L[8][8];
    for (int i = 0; i < 8; i++)
        for (int j = 0; j < 8; j++)
            L[i][j] = (g_acc[i*8+j] - 0.5 * g_acc[64+j]) / 64.0;
    double ce = 0.0;
    for (int i = 0; i < 8; i++) {
        double m = L[i][0];
        for (int j = 1; j < 8; j++) m = L[i][j] > m ? L[i][j] : m;
        double s = 0.0;
        for (int j = 0; j < 8; j++) s += exp(L[i][j] - m);
        ce += (m + log(s)) - L[i][i];
    }
    ce /= 8.0;
    double loss = ce * (2.0 * 64.0 / 8.0) * 2e-05;
    out[0] = (float)loss;
}

// =====================================================================
extern "C" void kernel_launch(void* const* d_in, const int* in_sizes, int n_in,
                              void* d_out, int out_size) {
    const float* S  = (const float*)d_in[0];
    const float* T  = (const float*)d_in[1];
    const float* Wa = (const float*)d_in[2];
    const float* ba = (const float*)d_in[3];
    const float* W1 = (const float*)d_in[4];
    const float* b1 = (const float*)d_in[5];
    const float* W2 = (const float*)d_in[6];
    const float* b2 = (const float*)d_in[7];
    float* out = (float*)d_out;

    float* tbuf;
    cudaGetSymbolAddress((void**)&tbuf, g_t);
    __nv_bfloat16 *waH, *waL, *w1p, *w2p, *mHi, *mLo, *g1Hi, *g1Lo;
    cudaGetSymbolAddress((void**)&waH, g_WaHi);
    cudaGetSymbolAddress((void**)&waL, g_WaLo);
    cudaGetSymbolAddress((void**)&w1p, g_W1p);
    cudaGetSymbolAddress((void**)&w2p, g_W2p);
    cudaGetSymbolAddress((void**)&mHi, g_mHi);
    cudaGetSymbolAddress((void**)&mLo, g_mLo);
    cudaGetSymbolAddress((void**)&g1Hi, g_g1Hi);
    cudaGetSymbolAddress((void**)&g1Lo, g_g1Lo);

    cudaFuncSetAttribute(conv1_mma, cudaFuncAttributeMaxDynamicSharedMemorySize, 65536);
    cudaFuncSetAttribute(conv_cp<true,  true >, cudaFuncAttributeMaxDynamicSharedMemorySize, 98304);
    cudaFuncSetAttribute(conv_cp<false, false>, cudaFuncAttributeMaxDynamicSharedMemorySize, 98304);

    init_kernel<<<1, 128>>>();
    {
        int total = 256*128 + 9*8*2*8192;
        wprep_kernel<<<(total + 255) / 256, 256>>>(Wa, W1, W2);
    }
    dim3 gg(256, 2);
    conv1_mma<<<gg, 256, 65536>>>(waH, waL, ba, S, mHi, mLo);
    conv_cp<true,  true ><<<gg, 256, 98304>>>(w1p, b1, mHi,  mLo,  nullptr, g1Hi, g1Lo);
    conv_cp<false, false><<<gg, 256, 98304>>>(w2p, b2, g1Hi, g1Lo, tbuf,    nullptr, nullptr);

    dot_kernel<<<DTOT / 2048, 256>>>(T, tbuf);
    finalize_kernel<<<1, 1>>>(out);
}

// round 7
// speedup vs baseline: 3.1246x; 1.2595x over previous
#include <cuda_runtime.h>
#include <cuda_bf16.h>
#include <cstdint>
#include <math.h>

#define NIMG 8
#define CS   128
#define CT   256
#define PIX  4096           // 64*64
#define DTOT (CT*PIX)       // per image

// ---- scratch (__device__ globals; no allocation allowed) ----
__device__ float g_t[(size_t)NIMG*CT*PIX];
__device__ double g_acc[72];

// conv1 output: COMPACT odd-parity pixels only, [img][kc(8)][pix2048][32ch]
__device__ __align__(16) __nv_bfloat16 g_mHi[(size_t)NIMG*8*2048*32];
__device__ __align__(16) __nv_bfloat16 g_mLo[(size_t)NIMG*8*2048*32];
// gen1 output: dense [img][kc(8)][pix4096][32ch]
__device__ __align__(16) __nv_bfloat16 g_g1Hi[(size_t)NIMG*8*4096*32];
__device__ __align__(16) __nv_bfloat16 g_g1Lo[(size_t)NIMG*8*4096*32];

// conv1 weights (row-major hi/lo)
__device__ __align__(16) __nv_bfloat16 g_WaHi[256*128], g_WaLo[256*128];
// conv2/3 weights packed in SMEM-tile order:
// block = (tap*8+kc)*2+mb ; within 8192: r(0..1023)*8+j
// r: hilo=r>>9, khalf=(r>>7)&3, co=r&127
__device__ __align__(16) __nv_bfloat16 g_W1p[9*8*2*8192];
__device__ __align__(16) __nv_bfloat16 g_W2p[9*8*2*8192];

// =====================================================================
// helpers (sm_80+ baseline PTX)
// =====================================================================
__device__ __forceinline__ uint32_t smem_u32(const void* p) {
    uint32_t a;
    asm("{ .reg .u64 t; cvta.to.shared.u64 t, %1; cvt.u32.u64 %0, t; }" : "=r"(a) : "l"(p));
    return a;
}
__device__ __forceinline__ void ldsm4(uint32_t* r, uint32_t addr) {
    asm volatile("ldmatrix.sync.aligned.m8n8.x4.shared.b16 {%0,%1,%2,%3}, [%4];"
                 : "=r"(r[0]), "=r"(r[1]), "=r"(r[2]), "=r"(r[3]) : "r"(addr));
}
__device__ __forceinline__ void mma16816(float* c, const uint32_t* a, uint32_t b0, uint32_t b1) {
    asm volatile("mma.sync.aligned.m16n8k16.row.col.f32.bf16.bf16.f32 "
                 "{%0,%1,%2,%3}, {%4,%5,%6,%7}, {%8,%9}, {%0,%1,%2,%3};"
                 : "+f"(c[0]), "+f"(c[1]), "+f"(c[2]), "+f"(c[3])
                 : "r"(a[0]), "r"(a[1]), "r"(a[2]), "r"(a[3]), "r"(b0), "r"(b1));
}
__device__ __forceinline__ void cp16(uint32_t dst, const void* src, uint32_t sz) {
    asm volatile("cp.async.cg.shared.global [%0], [%1], 16, %2;"
                 :: "r"(dst), "l"(src), "r"(sz) : "memory");
}
__device__ __forceinline__ void cp_commit() {
    asm volatile("cp.async.commit_group;" ::: "memory");
}
__device__ __forceinline__ void cp_wait1() {
    asm volatile("cp.async.wait_group 1;" ::: "memory");
}
__device__ __forceinline__ void bf16split(float v, __nv_bfloat16& h, __nv_bfloat16& l) {
    h = __float2bfloat16(v);
    l = __float2bfloat16(v - __bfloat162float(h));
}

// =====================================================================
// Weight prep
// =====================================================================
__global__ void wprep_kernel(const float* __restrict__ Wa, const float* __restrict__ W1,
                             const float* __restrict__ W2) {
    int t = blockIdx.x * blockDim.x + threadIdx.x;
    if (t < 256*128) {
        float v = Wa[t];
        __nv_bfloat16 h, l;
        bf16split(v, h, l);
        g_WaHi[t] = h; g_WaLo[t] = l;
    }
    int u = t - 256*128;
    if (u >= 0 && u < 9*8*2*8192) {
        int chunk  = u >> 13;
        int within = u & 8191;
        int r = within >> 3, j = within & 7;
        int tap = chunk >> 4;
        int kc  = (chunk >> 1) & 7;
        int mb  = chunk & 1;
        int hilo  = r >> 9;
        int khalf = (r >> 7) & 3;
        int co    = r & 127;
        int co_g  = mb * 128 + co;
        int ci    = kc * 32 + khalf * 8 + j;
        int src   = co_g * 2304 + ci * 9 + tap;
        {
            __nv_bfloat16 h, l;
            bf16split(W1[src], h, l);
            g_W1p[u] = hilo ? l : h;
        }
        {
            __nv_bfloat16 h, l;
            bf16split(W2[src], h, l);
            g_W2p[u] = hilo ? l : h;
        }
    }
}

__global__ void init_kernel() {
    if (threadIdx.x < 72) g_acc[threadIdx.x] = 0.0;
}

// =====================================================================
// conv1 (1x1, K=128): computes ONLY odd-parity pixels (the mask kills
// the rest). grid (128, 2): x = img*16 + ptile(compact). Output compact
// [kc][pix2048][32] hi/lo planes.
// =====================================================================
__global__ __launch_bounds__(256, 2)
void conv1_mma(const __nv_bfloat16* __restrict__ Whi, const __nv_bfloat16* __restrict__ Wlo,
               const float* __restrict__ bias, const float* __restrict__ in,
               __nv_bfloat16* __restrict__ outHi, __nv_bfloat16* __restrict__ outLo) {
    extern __shared__ char sm[];
    const int tid  = threadIdx.x;
    const int lane = tid & 31, wid = tid >> 5;
    const int m0   = blockIdx.y * 128;
    const int bx   = blockIdx.x;
    const int img  = bx >> 4;
    const int pix0 = (bx & 15) * 128;     // compact pixel base
    const float* inImg = in + (size_t)img * CS * PIX;

    constexpr int NCH = CS / 32;  // 4

    const int a_row = tid >> 1;
    const int a_k0  = (tid & 1) * 16;
    const int b_n   = tid & 127;
    const int b_sg  = tid >> 7;
    // compact pixel -> (h, w) for this loader thread
    const int cpx  = pix0 + b_n;
    const int ch_h = cpx >> 5;
    const int ch_w = 2 * (cpx & 31) + ((ch_h + 1) & 1);
    const int bsrc = ch_h * 64 + ch_w;

    uint4 rAh[2], rAl[2];
    float rB[16];

    auto ldg_chunk = [&](int it) {
        const int c0 = it * 32;
        size_t aoff = (size_t)(m0 + a_row) * CS + c0 + a_k0;
        rAh[0] = *(const uint4*)(Whi + aoff);
        rAh[1] = *(const uint4*)(Whi + aoff + 8);
        rAl[0] = *(const uint4*)(Wlo + aoff);
        rAl[1] = *(const uint4*)(Wlo + aoff + 8);
        const float* p = inImg + (size_t)(c0 + b_sg * 16) * PIX + bsrc;
#pragma unroll
        for (int q = 0; q < 16; q++)
            rB[q] = __ldg(p + (size_t)q * PIX);
    };

    auto sts_chunk = [&](int s) {
        char* Ahi = sm + s * 32768;
        char* Alo = Ahi + 8192;
        char* Bhi = Ahi + 16384;
        char* Blo = Ahi + 24576;
        const int kh0 = a_k0 >> 3;
        *(uint4*)(Ahi + (kh0    ) * 2048 + a_row * 16) = rAh[0];
        *(uint4*)(Ahi + (kh0 + 1) * 2048 + a_row * 16) = rAh[1];
        *(uint4*)(Alo + (kh0    ) * 2048 + a_row * 16) = rAl[0];
        *(uint4*)(Alo + (kh0 + 1) * 2048 + a_row * 16) = rAl[1];
#pragma unroll
        for (int g = 0; g < 2; g++) {
            uint32_t hp[4], lp[4];
#pragma unroll
            for (int jp = 0; jp < 4; jp++) {
                float x0 = rB[g * 8 + 2 * jp], x1 = rB[g * 8 + 2 * jp + 1];
                __nv_bfloat16 hb0, lb0, hb1, lb1;
                bf16split(x0, hb0, lb0);
                bf16split(x1, hb1, lb1);
                hp[jp] = (uint32_t)__bfloat16_as_ushort(hb0)
                       | ((uint32_t)__bfloat16_as_ushort(hb1) << 16);
                lp[jp] = (uint32_t)__bfloat16_as_ushort(lb0)
                       | ((uint32_t)__bfloat16_as_ushort(lb1) << 16);
            }
            const int kh = b_sg * 2 + g;
            *(uint4*)(Bhi + kh * 2048 + b_n * 16) = make_uint4(hp[0], hp[1], hp[2], hp[3]);
            *(uint4*)(Blo + kh * 2048 + b_n * 16) = make_uint4(lp[0], lp[1], lp[2], lp[3]);
        }
    };

    float acc[4][4][4];
#pragma unroll
    for (int i = 0; i < 4; i++)
#pragma unroll
        for (int j = 0; j < 4; j++)
#pragma unroll
            for (int k = 0; k < 4; k++) acc[i][j][k] = 0.f;

    const int warp_m = wid & 1;
    const int warp_n = wid >> 1;
    const uint32_t smem0 = smem_u32(sm);
    const int lrow = (lane & 7) + ((lane >> 3) & 1) * 8;
    const int lkh  = (lane >> 4);

    ldg_chunk(0);
    sts_chunk(0);
    __syncthreads();

    for (int it = 0; it < NCH; ++it) {
        if (it + 1 < NCH) ldg_chunk(it + 1);
        const uint32_t S = smem0 + (it & 1) * 32768;
#pragma unroll
        for (int k16 = 0; k16 < 2; ++k16) {
            const uint32_t kbase = S + (k16 * 2 + lkh) * 2048;
            uint32_t bh[2][4], bl[2][4];
#pragma unroll
            for (int ng = 0; ng < 2; ++ng) {
                const uint32_t bd = kbase + 16384 + (warp_n * 32 + ng * 16 + lrow) * 16;
                ldsm4(bh[ng], bd);
                ldsm4(bl[ng], bd + 8192);
            }
#pragma unroll
            for (int mt = 0; mt < 4; ++mt) {
                uint32_t ah[4], al[4];
                const uint32_t ad = kbase + (warp_m * 64 + mt * 16 + lrow) * 16;
                ldsm4(ah, ad);
                ldsm4(al, ad + 8192);
                // pass-major: dependent MMAs spaced by 4 independents
#pragma unroll
                for (int nt = 0; nt < 4; ++nt)
                    mma16816(acc[mt][nt], ah, bh[nt >> 1][nt & 1], bh[nt >> 1][2 + (nt & 1)]);
#pragma unroll
                for (int nt = 0; nt < 4; ++nt)
                    mma16816(acc[mt][nt], ah, bl[nt >> 1][nt & 1], bl[nt >> 1][2 + (nt & 1)]);
#pragma unroll
                for (int nt = 0; nt < 4; ++nt)
                    mma16816(acc[mt][nt], al, bh[nt >> 1][nt & 1], bh[nt >> 1][2 + (nt & 1)]);
            }
        }
        if (it + 1 < NCH) sts_chunk((it + 1) & 1);
        __syncthreads();
    }

    // epilogue: bias only (all stored pixels are the kept parity)
    const int l4 = lane >> 2, l2 = lane & 3;
    const size_t imgbase = (size_t)img * 8 * 2048 * 32;
#pragma unroll
    for (int mt = 0; mt < 4; ++mt) {
        const int co0 = m0 + warp_m * 64 + mt * 16 + l4;
        const float bi0 = bias[co0], bi1 = bias[co0 + 8];
#pragma unroll
        for (int nt = 0; nt < 4; ++nt) {
            const int p = pix0 + warp_n * 32 + nt * 8 + l2 * 2;  // compact pixel
            float v0 = acc[mt][nt][0] + bi0;
            float v1 = acc[mt][nt][1] + bi0;
            float v2 = acc[mt][nt][2] + bi1;
            float v3 = acc[mt][nt][3] + bi1;
            const size_t o00 = imgbase + ((size_t)(co0 >> 5) * 2048 + p) * 32 + (co0 & 31);
            const size_t o10 = imgbase + ((size_t)((co0 + 8) >> 5) * 2048 + p) * 32 + ((co0 + 8) & 31);
            __nv_bfloat16 h, l;
            bf16split(v0, h, l); outHi[o00]      = h; outLo[o00]      = l;
            bf16split(v1, h, l); outHi[o00 + 32] = h; outLo[o00 + 32] = l;
            bf16split(v2, h, l); outHi[o10]      = h; outLo[o10]      = l;
            bf16split(v3, h, l); outHi[o10 + 32] = h; outLo[o10 + 32] = l;
        }
    }
}

// =====================================================================
// conv2 (gen1, 3x3): polyphase over checkerboard sparsity.
// grid (256, 2): x = img*32 + P*16 + htile. CTA computes 128 co x
// 128 output pixels of parity P (4 rows x 32 pixels). Tap set:
// P=0 -> tap ids {1,3,5,7}; P=1 -> {0,2,4,6,8}. Input is compact
// odd-pixel planes. Output dense hi/lo planes + relu.
// =====================================================================
__global__ __launch_bounds__(256, 2)
void conv2_poly(const __nv_bfloat16* __restrict__ Wp,
                const float* __restrict__ bias,
                const __nv_bfloat16* __restrict__ actHi,
                const __nv_bfloat16* __restrict__ actLo,
                __nv_bfloat16* __restrict__ outHi,
                __nv_bfloat16* __restrict__ outLo) {
    extern __shared__ char sm[];
    const int tid  = threadIdx.x;
    const int lane = tid & 31, wid = tid >> 5;
    const int mb   = blockIdx.y;
    const int m0   = mb * 128;
    const int bx   = blockIdx.x;
    const int img  = bx >> 5;
    const int rem  = bx & 31;
    const int P    = rem >> 4;
    const int h0   = (rem & 15) * 4;

    const int NT  = 4 + P;        // taps contributing to this parity
    const int NCH = NT * 8;
    const uint32_t smem0 = smem_u32(sm);

    // B-row constants: r = khalf*128 + n
    const int r0 = tid, r1 = tid + 256;
    const int kh_r0 = r0 >> 7, n_r0 = r0 & 127;
    const int kh_r1 = r1 >> 7, n_r1 = r1 & 127;

    auto issue = [&](int it) {
        const int st = it % 3;
        const uint32_t stage = smem0 + st * 32768;
        const int tap_t = it % NT, kc = it / NT;
        const int tapid = P ? (2 * tap_t) : (2 * tap_t + 1);
        const int dh = tapid / 3 - 1, dw = tapid % 3 - 1;
        // A: packed weights
        const __nv_bfloat16* asrc = Wp + ((size_t)((tapid * 8 + kc) * 2 + mb)) * 8192 + tid * 8;
#pragma unroll
        for (int i = 0; i < 4; i++)
            cp16(stage + (tid + 256 * i) * 16, asrc + 2048 * i, 16u);
        // B: compact odd-pixel input
        const size_t actbase = ((size_t)(img * 8 + kc)) * 2048 * 32;
        {
            const int row = h0 + (n_r0 >> 5);
            const int ow  = 2 * (n_r0 & 31) + ((P + row) & 1);
            const int h = row + dh, w = ow + dw;
            const bool ok = ((unsigned)h < 64u) & ((unsigned)w < 64u);
            const int ci = (w - ((h + 1) & 1)) >> 1;
            const size_t so = ok ? (actbase + (size_t)(h * 32 + ci) * 32 + kh_r0 * 8) : 0;
            const uint32_t d = stage + 16384 + r0 * 16;
            cp16(d,        actHi + so, ok ? 16u : 0u);
            cp16(d + 8192, actLo + so, ok ? 16u : 0u);
        }
        {
            const int row = h0 + (n_r1 >> 5);
            const int ow  = 2 * (n_r1 & 31) + ((P + row) & 1);
            const int h = row + dh, w = ow + dw;
            const bool ok = ((unsigned)h < 64u) & ((unsigned)w < 64u);
            const int ci = (w - ((h + 1) & 1)) >> 1;
            const size_t so = ok ? (actbase + (size_t)(h * 32 + ci) * 32 + kh_r1 * 8) : 0;
            const uint32_t d = stage + 16384 + r1 * 16;
            cp16(d,        actHi + so, ok ? 16u : 0u);
            cp16(d + 8192, actLo + so, ok ? 16u : 0u);
        }
    };

    float acc[4][4][4];
#pragma unroll
    for (int i = 0; i < 4; i++)
#pragma unroll
        for (int j = 0; j < 4; j++)
#pragma unroll
            for (int k = 0; k < 4; k++) acc[i][j][k] = 0.f;

    const int warp_m = wid & 1;
    const int warp_n = wid >> 1;
    const int lrow = (lane & 7) + ((lane >> 3) & 1) * 8;
    const int lkh  = (lane >> 4);

    issue(0); cp_commit();
    issue(1); cp_commit();

    for (int it = 0; it < NCH; ++it) {
        cp_wait1();
        __syncthreads();
        if (it + 2 < NCH) issue(it + 2);
        cp_commit();

        const uint32_t S = smem0 + (it % 3) * 32768;
#pragma unroll
        for (int k16 = 0; k16 < 2; ++k16) {
            const uint32_t kbase = S + (k16 * 2 + lkh) * 2048;
            uint32_t bh[2][4], bl[2][4];
#pragma unroll
            for (int ng = 0; ng < 2; ++ng) {
                const uint32_t bd = kbase + 16384 + (warp_n * 32 + ng * 16 + lrow) * 16;
                ldsm4(bh[ng], bd);
                ldsm4(bl[ng], bd + 8192);
            }
#pragma unroll
            for (int mt = 0; mt < 4; ++mt) {
                uint32_t ah[4], al[4];
                const uint32_t ad = kbase + (warp_m * 64 + mt * 16 + lrow) * 16;
                ldsm4(ah, ad);
                ldsm4(al, ad + 8192);
#pragma unroll
                for (int nt = 0; nt < 4; ++nt)
                    mma16816(acc[mt][nt], ah, bh[nt >> 1][nt & 1], bh[nt >> 1][2 + (nt & 1)]);
#pragma unroll
                for (int nt = 0; nt < 4; ++nt)
                    mma16816(acc[mt][nt], ah, bl[nt >> 1][nt & 1], bl[nt >> 1][2 + (nt & 1)]);
#pragma unroll
                for (int nt = 0; nt < 4; ++nt)
                    mma16816(acc[mt][nt], al, bh[nt >> 1][nt & 1], bh[nt >> 1][2 + (nt & 1)]);
            }
        }
    }

    // epilogue: bias + relu, scatter to dense planes (each warp owns one row)
    const int l4 = lane >> 2, l2 = lane & 3;
    const int row = h0 + warp_n;
    const int wpar = (P + row) & 1;
    const size_t imgbase = (size_t)img * 8 * 4096 * 32;
#pragma unroll
    for (int mt = 0; mt < 4; ++mt) {
        const int co0 = m0 + warp_m * 64 + mt * 16 + l4;
        const float bi0 = bias[co0], bi1 = bias[co0 + 8];
        const size_t cb0 = imgbase + (size_t)(co0 >> 5) * 4096 * 32 + (co0 & 31);
        const size_t cb1 = imgbase + (size_t)((co0 + 8) >> 5) * 4096 * 32 + ((co0 + 8) & 31);
#pragma unroll
        for (int nt = 0; nt < 4; ++nt) {
            const int j0 = nt * 8 + l2 * 2;
            const int pix0e = row * 64 + 2 * j0 + wpar;       // j0
            const int pix1e = pix0e + 2;                      // j0+1
            float v0 = fmaxf(acc[mt][nt][0] + bi0, 0.f);
            float v1 = fmaxf(acc[mt][nt][1] + bi0, 0.f);
            float v2 = fmaxf(acc[mt][nt][2] + bi1, 0.f);
            float v3 = fmaxf(acc[mt][nt][3] + bi1, 0.f);
            __nv_bfloat16 h, l;
            bf16split(v0, h, l); outHi[cb0 + (size_t)pix0e * 32] = h; outLo[cb0 + (size_t)pix0e * 32] = l;
            bf16split(v1, h, l); outHi[cb0 + (size_t)pix1e * 32] = h; outLo[cb0 + (size_t)pix1e * 32] = l;
            bf16split(v2, h, l); outHi[cb1 + (size_t)pix0e * 32] = h; outLo[cb1 + (size_t)pix0e * 32] = l;
            bf16split(v3, h, l); outHi[cb1 + (size_t)pix1e * 32] = h; outLo[cb1 + (size_t)pix1e * 32] = l;
        }
    }
}

// =====================================================================
// conv3 (3x3, dense input planes): cp.async 3-stage, fp32 output.
// =====================================================================
__global__ __launch_bounds__(256, 2)
void conv3_cp(const __nv_bfloat16* __restrict__ Wp,
              const float* __restrict__ bias,
              const __nv_bfloat16* __restrict__ actHi,
              const __nv_bfloat16* __restrict__ actLo,
              float* __restrict__ outF32) {
    extern __shared__ char sm[];
    const int tid  = threadIdx.x;
    const int lane = tid & 31, wid = tid >> 5;
    const int mb   = blockIdx.y;
    const int m0   = mb * 128;
    const int bx   = blockIdx.x;
    const int img  = bx >> 5;
    const int pix0 = (bx & 31) * 128;
    const int h0   = pix0 >> 6;

    constexpr int NCH = 72;
    const uint32_t smem0 = smem_u32(sm);

    const int r0 = tid, r1 = tid + 256;
    const int kh_r0 = r0 >> 7, px_r0 = r0 & 127;
    const int kh_r1 = r1 >> 7, px_r1 = r1 & 127;

    auto issue = [&](int it) {
        const int st = it % 3;
        const uint32_t stage = smem0 + st * 32768;
        const int tap = it % 9, kc = it / 9;
        const int dh = tap / 3 - 1, dw = tap % 3 - 1;
        const __nv_bfloat16* asrc = Wp + ((size_t)((tap * 8 + kc) * 2 + mb)) * 8192 + tid * 8;
#pragma unroll
        for (int i = 0; i < 4; i++)
            cp16(stage + (tid + 256 * i) * 16, asrc + 2048 * i, 16u);
        const size_t actbase = ((size_t)(img * 8 + kc)) * 4096 * 32;
        {
            const int h = h0 + (px_r0 >> 6) + dh, w = (px_r0 & 63) + dw;
            const bool ok = ((unsigned)h < 64u) & ((unsigned)w < 64u);
            const size_t so = ok ? (actbase + (size_t)(h * 64 + w) * 32 + kh_r0 * 8) : 0;
            const uint32_t d = stage + 16384 + r0 * 16;
            cp16(d,        actHi + so, ok ? 16u : 0u);
            cp16(d + 8192, actLo + so, ok ? 16u : 0u);
        }
        {
            const int h = h0 + (px_r1 >> 6) + dh, w = (px_r1 & 63) + dw;
            const bool ok = ((unsigned)h < 64u) & ((unsigned)w < 64u);
            const size_t so = ok ? (actbase + (size_t)(h * 64 + w) * 32 + kh_r1 * 8) : 0;
            const uint32_t d = stage + 16384 + r1 * 16;
            cp16(d,        actHi + so, ok ? 16u : 0u);
            cp16(d + 8192, actLo + so, ok ? 16u : 0u);
        }
    };

    float acc[4][4][4];
#pragma unroll
    for (int i = 0; i < 4; i++)
#pragma unroll
        for (int j = 0; j < 4; j++)
#pragma unroll
            for (int k = 0; k < 4; k++) acc[i][j][k] = 0.f;

    const int warp_m = wid & 1;
    const int warp_n = wid >> 1;
    const int lrow = (lane & 7) + ((lane >> 3) & 1) * 8;
    const int lkh  = (lane >> 4);

    issue(0); cp_commit();
    issue(1); cp_commit();

    for (int it = 0; it < NCH; ++it) {
        cp_wait1();
        __syncthreads();
        if (it + 2 < NCH) issue(it + 2);
        cp_commit();

        const uint32_t S = smem0 + (it % 3) * 32768;
#pragma unroll
        for (int k16 = 0; k16 < 2; ++k16) {
            const uint32_t kbase = S + (k16 * 2 + lkh) * 2048;
            uint32_t bh[2][4], bl[2][4];
#pragma unroll
            for (int ng = 0; ng < 2; ++ng) {
                const uint32_t bd = kbase + 16384 + (warp_n * 32 + ng * 16 + lrow) * 16;
                ldsm4(bh[ng], bd);
                ldsm4(bl[ng], bd + 8192);
            }
#pragma unroll
            for (int mt = 0; mt < 4; ++mt) {
                uint32_t ah[4], al[4];
                const uint32_t ad = kbase + (warp_m * 64 + mt * 16 + lrow) * 16;
                ldsm4(ah, ad);
                ldsm4(al, ad + 8192);
#pragma unroll
                for (int nt = 0; nt < 4; ++nt)
                    mma16816(acc[mt][nt], ah, bh[nt >> 1][nt & 1], bh[nt >> 1][2 + (nt & 1)]);
#pragma unroll
                for (int nt = 0; nt < 4; ++nt)
                    mma16816(acc[mt][nt], ah, bl[nt >> 1][nt & 1], bl[nt >> 1][2 + (nt & 1)]);
#pragma unroll
                for (int nt = 0; nt < 4; ++nt)
                    mma16816(acc[mt][nt], al, bh[nt >> 1][nt & 1], bh[nt >> 1][2 + (nt & 1)]);
            }
        }
    }

    const int l4 = lane >> 2, l2 = lane & 3;
    float* outImg = outF32 + (size_t)img * CT * PIX;
#pragma unroll
    for (int mt = 0; mt < 4; ++mt) {
        const int co0 = m0 + warp_m * 64 + mt * 16 + l4;
        const float bi0 = bias[co0], bi1 = bias[co0 + 8];
#pragma unroll
        for (int nt = 0; nt < 4; ++nt) {
            const int p = pix0 + warp_n * 32 + nt * 8 + l2 * 2;
            float v0 = acc[mt][nt][0] + bi0;
            float v1 = acc[mt][nt][1] + bi0;
            float v2 = acc[mt][nt][2] + bi1;
            float v3 = acc[mt][nt][3] + bi1;
            *(float2*)(outImg + (size_t)co0 * PIX + p)       = make_float2(v0, v1);
            *(float2*)(outImg + (size_t)(co0 + 8) * PIX + p) = make_float2(v2, v3);
        }
    }
}

// =====================================================================
// pairwise dots + target norms (unchanged, verified)
// =====================================================================
__global__ __launch_bounds__(256)
void dot_kernel(const float* __restrict__ p, const float* __restrict__ t) {
    const int tid = threadIdx.x;
    const int d0  = blockIdx.x * 2048 + tid;

    float dacc[8][8];
    float tn[8];
#pragma unroll
    for (int i = 0; i < 8; i++) {
        tn[i] = 0.f;
#pragma unroll
        for (int j = 0; j < 8; j++) dacc[i][j] = 0.f;
    }
#pragma unroll 2
    for (int it = 0; it < 8; it++) {
        int d = d0 + it * 256;
        float pv[8], tv[8];
#pragma unroll
        for (int i = 0; i < 8; i++) {
            pv[i] = __ldg(p + (size_t)i * DTOT + d);
            tv[i] = __ldg(t + (size_t)i * DTOT + d);
        }
#pragma unroll
        for (int j = 0; j < 8; j++) tn[j] = fmaf(tv[j], tv[j], tn[j]);
#pragma unroll
        for (int i = 0; i < 8; i++)
#pragma unroll
            for (int j = 0; j < 8; j++)
                dacc[i][j] = fmaf(pv[i], tv[j], dacc[i][j]);
    }
    __shared__ float red[8][72];
    const int lane = tid & 31, warp = tid >> 5;
#pragma unroll
    for (int i = 0; i < 8; i++)
#pragma unroll
        for (int j = 0; j < 8; j++) {
            float v = dacc[i][j];
#pragma unroll
            for (int s = 16; s; s >>= 1) v += __shfl_xor_sync(0xFFFFFFFFu, v, s);
            if (lane == 0) red[warp][i*8+j] = v;
        }
#pragma unroll
    for (int j = 0; j < 8; j++) {
        float v = tn[j];
#pragma unroll
        for (int s = 16; s; s >>= 1) v += __shfl_xor_sync(0xFFFFFFFFu, v, s);
        if (lane == 0) red[warp][64+j] = v;
    }
    __syncthreads();
    if (tid < 72) {
        double s = 0.0;
#pragma unroll
        for (int w = 0; w < 8; w++) s += (double)red[w][tid];
        atomicAdd(&g_acc[tid], s);
    }
}

__global__ void finalize_kernel(float* __restrict__ out) {
    if (threadIdx.x != 0 || blockIdx.x != 0) return;
    double L[8][8];
    for (int i = 0; i < 8; i++)
        for (int j = 0; j < 8; j++)
            L[i][j] = (g_acc[i*8+j] - 0.5 * g_acc[64+j]) / 64.0;
    double ce = 0.0;
    for (int i = 0; i < 8; i++) {
        double m = L[i][0];
        for (int j = 1; j < 8; j++) m = L[i][j] > m ? L[i][j] : m;
        double s = 0.0;
        for (int j = 0; j < 8; j++) s += exp(L[i][j] - m);
        ce += (m + log(s)) - L[i][i];
    }
    ce /= 8.0;
    double loss = ce * (2.0 * 64.0 / 8.0) * 2e-05;
    out[0] = (float)loss;
}

// =====================================================================
extern "C" void kernel_launch(void* const* d_in, const int* in_sizes, int n_in,
                              void* d_out, int out_size) {
    const float* S  = (const float*)d_in[0];
    const float* T  = (const float*)d_in[1];
    const float* Wa = (const float*)d_in[2];
    const float* ba = (const float*)d_in[3];
    const float* W1 = (const float*)d_in[4];
    const float* b1 = (const float*)d_in[5];
    const float* W2 = (const float*)d_in[6];
    const float* b2 = (const float*)d_in[7];
    float* out = (float*)d_out;

    float* tbuf;
    cudaGetSymbolAddress((void**)&tbuf, g_t);
    __nv_bfloat16 *waH, *waL, *w1p, *w2p, *mHi, *mLo, *g1Hi, *g1Lo;
    cudaGetSymbolAddress((void**)&waH, g_WaHi);
    cudaGetSymbolAddress((void**)&waL, g_WaLo);
    cudaGetSymbolAddress((void**)&w1p, g_W1p);
    cudaGetSymbolAddress((void**)&w2p, g_W2p);
    cudaGetSymbolAddress((void**)&mHi, g_mHi);
    cudaGetSymbolAddress((void**)&mLo, g_mLo);
    cudaGetSymbolAddress((void**)&g1Hi, g_g1Hi);
    cudaGetSymbolAddress((void**)&g1Lo, g_g1Lo);

    cudaFuncSetAttribute(conv1_mma,  cudaFuncAttributeMaxDynamicSharedMemorySize, 65536);
    cudaFuncSetAttribute(conv2_poly, cudaFuncAttributeMaxDynamicSharedMemorySize, 98304);
    cudaFuncSetAttribute(conv3_cp,   cudaFuncAttributeMaxDynamicSharedMemorySize, 98304);

    init_kernel<<<1, 128>>>();
    {
        int total = 256*128 + 9*8*2*8192;
        wprep_kernel<<<(total + 255) / 256, 256>>>(Wa, W1, W2);
    }
    conv1_mma <<<dim3(128, 2), 256, 65536>>>(waH, waL, ba, S, mHi, mLo);
    conv2_poly<<<dim3(256, 2), 256, 98304>>>(w1p, b1, mHi, mLo, g1Hi, g1Lo);
    conv3_cp  <<<dim3(256, 2), 256, 98304>>>(w2p, b2, g1Hi, g1Lo, tbuf);

    dot_kernel<<<DTOT / 2048, 256>>>(T, tbuf);
    finalize_kernel<<<1, 1>>>(out);
}

// round 8
// speedup vs baseline: 3.1962x; 1.0229x over previous
#include <cuda_runtime.h>
#include <cuda_bf16.h>
#include <cstdint>
#include <math.h>

#define NIMG 8
#define CS   128
#define CT   256
#define PIX  4096           // 64*64
#define DTOT (CT*PIX)       // per image

// ---- scratch (__device__ globals; no allocation allowed) ----
__device__ float g_t[(size_t)NIMG*CT*PIX];
__device__ double g_acc[72];

// conv1 output: COMPACT odd-parity pixels only, [img][kc(8)][pix2048][32ch]
__device__ __align__(16) __nv_bfloat16 g_mHi[(size_t)NIMG*8*2048*32];
__device__ __align__(16) __nv_bfloat16 g_mLo[(size_t)NIMG*8*2048*32];
// gen1 output: dense [img][kc(8)][pix4096][32ch]
__device__ __align__(16) __nv_bfloat16 g_g1Hi[(size_t)NIMG*8*4096*32];
__device__ __align__(16) __nv_bfloat16 g_g1Lo[(size_t)NIMG*8*4096*32];

// conv1 weights (row-major hi/lo)
__device__ __align__(16) __nv_bfloat16 g_WaHi[256*128], g_WaLo[256*128];
// conv2/3 weights packed for 512-thread BK=64 stages:
// chunk = tap*4 + kc2 (36 chunks); within 32768 elems: r(0..4095)*8 + j
// r = hilo*2048 + khalf*256 + co   (khalf: 8 groups of 8 ci within BK=64)
__device__ __align__(16) __nv_bfloat16 g_W1p[36*32768];
__device__ __align__(16) __nv_bfloat16 g_W2p[36*32768];

// =====================================================================
// helpers (sm_80+ baseline PTX)
// =====================================================================
__device__ __forceinline__ uint32_t smem_u32(const void* p) {
    uint32_t a;
    asm("{ .reg .u64 t; cvta.to.shared.u64 t, %1; cvt.u32.u64 %0, t; }" : "=r"(a) : "l"(p));
    return a;
}
__device__ __forceinline__ void ldsm4(uint32_t* r, uint32_t addr) {
    asm volatile("ldmatrix.sync.aligned.m8n8.x4.shared.b16 {%0,%1,%2,%3}, [%4];"
                 : "=r"(r[0]), "=r"(r[1]), "=r"(r[2]), "=r"(r[3]) : "r"(addr));
}
__device__ __forceinline__ void mma16816(float* c, const uint32_t* a, uint32_t b0, uint32_t b1) {
    asm volatile("mma.sync.aligned.m16n8k16.row.col.f32.bf16.bf16.f32 "
                 "{%0,%1,%2,%3}, {%4,%5,%6,%7}, {%8,%9}, {%0,%1,%2,%3};"
                 : "+f"(c[0]), "+f"(c[1]), "+f"(c[2]), "+f"(c[3])
                 : "r"(a[0]), "r"(a[1]), "r"(a[2]), "r"(a[3]), "r"(b0), "r"(b1));
}
__device__ __forceinline__ void cp16(uint32_t dst, const void* src, uint32_t sz) {
    asm volatile("cp.async.cg.shared.global [%0], [%1], 16, %2;"
                 :: "r"(dst), "l"(src), "r"(sz) : "memory");
}
__device__ __forceinline__ void cp_commit() {
    asm volatile("cp.async.commit_group;" ::: "memory");
}
__device__ __forceinline__ void cp_wait1() {
    asm volatile("cp.async.wait_group 1;" ::: "memory");
}
__device__ __forceinline__ void bf16split(float v, __nv_bfloat16& h, __nv_bfloat16& l) {
    h = __float2bfloat16(v);
    l = __float2bfloat16(v - __bfloat162float(h));
}

// =====================================================================
// Weight prep (new 512-thread BK=64 packing)
// =====================================================================
__global__ void wprep_kernel(const float* __restrict__ Wa, const float* __restrict__ W1,
                             const float* __restrict__ W2) {
    int t = blockIdx.x * blockDim.x + threadIdx.x;
    if (t < 256*128) {
        float v = Wa[t];
        __nv_bfloat16 h, l;
        bf16split(v, h, l);
        g_WaHi[t] = h; g_WaLo[t] = l;
    }
    int u = t - 256*128;
    if (u >= 0 && u < 36*32768) {
        int chunk  = u >> 15;
        int within = u & 32767;
        int r = within >> 3, j = within & 7;
        int tap = chunk >> 2;
        int kc2 = chunk & 3;
        int hilo  = r >> 11;
        int khalf = (r >> 8) & 7;
        int co    = r & 255;
        int ci    = kc2 * 64 + khalf * 8 + j;
        int src   = co * 2304 + ci * 9 + tap;
        {
            __nv_bfloat16 h, l;
            bf16split(W1[src], h, l);
            g_W1p[u] = hilo ? l : h;
        }
        {
            __nv_bfloat16 h, l;
            bf16split(W2[src], h, l);
            g_W2p[u] = hilo ? l : h;
        }
    }
}

__global__ void init_kernel() {
    if (threadIdx.x < 72) g_acc[threadIdx.x] = 0.0;
}

// =====================================================================
// conv1 (1x1, K=128): odd-parity pixels only (verified in R7).
// =====================================================================
__global__ __launch_bounds__(256, 2)
void conv1_mma(const __nv_bfloat16* __restrict__ Whi, const __nv_bfloat16* __restrict__ Wlo,
               const float* __restrict__ bias, const float* __restrict__ in,
               __nv_bfloat16* __restrict__ outHi, __nv_bfloat16* __restrict__ outLo) {
    extern __shared__ char sm[];
    const int tid  = threadIdx.x;
    const int lane = tid & 31, wid = tid >> 5;
    const int m0   = blockIdx.y * 128;
    const int bx   = blockIdx.x;
    const int img  = bx >> 4;
    const int pix0 = (bx & 15) * 128;
    const float* inImg = in + (size_t)img * CS * PIX;

    constexpr int NCH = CS / 32;  // 4

    const int a_row = tid >> 1;
    const int a_k0  = (tid & 1) * 16;
    const int b_n   = tid & 127;
    const int b_sg  = tid >> 7;
    const int cpx  = pix0 + b_n;
    const int ch_h = cpx >> 5;
    const int ch_w = 2 * (cpx & 31) + ((ch_h + 1) & 1);
    const int bsrc = ch_h * 64 + ch_w;

    uint4 rAh[2], rAl[2];
    float rB[16];

    auto ldg_chunk = [&](int it) {
        const int c0 = it * 32;
        size_t aoff = (size_t)(m0 + a_row) * CS + c0 + a_k0;
        rAh[0] = *(const uint4*)(Whi + aoff);
        rAh[1] = *(const uint4*)(Whi + aoff + 8);
        rAl[0] = *(const uint4*)(Wlo + aoff);
        rAl[1] = *(const uint4*)(Wlo + aoff + 8);
        const float* p = inImg + (size_t)(c0 + b_sg * 16) * PIX + bsrc;
#pragma unroll
        for (int q = 0; q < 16; q++)
            rB[q] = __ldg(p + (size_t)q * PIX);
    };

    auto sts_chunk = [&](int s) {
        char* Ahi = sm + s * 32768;
        char* Alo = Ahi + 8192;
        char* Bhi = Ahi + 16384;
        char* Blo = Ahi + 24576;
        const int kh0 = a_k0 >> 3;
        *(uint4*)(Ahi + (kh0    ) * 2048 + a_row * 16) = rAh[0];
        *(uint4*)(Ahi + (kh0 + 1) * 2048 + a_row * 16) = rAh[1];
        *(uint4*)(Alo + (kh0    ) * 2048 + a_row * 16) = rAl[0];
        *(uint4*)(Alo + (kh0 + 1) * 2048 + a_row * 16) = rAl[1];
#pragma unroll
        for (int g = 0; g < 2; g++) {
            uint32_t hp[4], lp[4];
#pragma unroll
            for (int jp = 0; jp < 4; jp++) {
                float x0 = rB[g * 8 + 2 * jp], x1 = rB[g * 8 + 2 * jp + 1];
                __nv_bfloat16 hb0, lb0, hb1, lb1;
                bf16split(x0, hb0, lb0);
                bf16split(x1, hb1, lb1);
                hp[jp] = (uint32_t)__bfloat16_as_ushort(hb0)
                       | ((uint32_t)__bfloat16_as_ushort(hb1) << 16);
                lp[jp] = (uint32_t)__bfloat16_as_ushort(lb0)
                       | ((uint32_t)__bfloat16_as_ushort(lb1) << 16);
            }
            const int kh = b_sg * 2 + g;
            *(uint4*)(Bhi + kh * 2048 + b_n * 16) = make_uint4(hp[0], hp[1], hp[2], hp[3]);
            *(uint4*)(Blo + kh * 2048 + b_n * 16) = make_uint4(lp[0], lp[1], lp[2], lp[3]);
        }
    };

    float acc[4][4][4];
#pragma unroll
    for (int i = 0; i < 4; i++)
#pragma unroll
        for (int j = 0; j < 4; j++)
#pragma unroll
            for (int k = 0; k < 4; k++) acc[i][j][k] = 0.f;

    const int warp_m = wid & 1;
    const int warp_n = wid >> 1;
    const uint32_t smem0 = smem_u32(sm);
    const int lrow = (lane & 7) + ((lane >> 3) & 1) * 8;
    const int lkh  = (lane >> 4);

    ldg_chunk(0);
    sts_chunk(0);
    __syncthreads();

    for (int it = 0; it < NCH; ++it) {
        if (it + 1 < NCH) ldg_chunk(it + 1);
        const uint32_t S = smem0 + (it & 1) * 32768;
#pragma unroll
        for (int k16 = 0; k16 < 2; ++k16) {
            const uint32_t kbase = S + (k16 * 2 + lkh) * 2048;
            uint32_t bh[2][4], bl[2][4];
#pragma unroll
            for (int ng = 0; ng < 2; ++ng) {
                const uint32_t bd = kbase + 16384 + (warp_n * 32 + ng * 16 + lrow) * 16;
                ldsm4(bh[ng], bd);
                ldsm4(bl[ng], bd + 8192);
            }
#pragma unroll
            for (int mt = 0; mt < 4; ++mt) {
                uint32_t ah[4], al[4];
                const uint32_t ad = kbase + (warp_m * 64 + mt * 16 + lrow) * 16;
                ldsm4(ah, ad);
                ldsm4(al, ad + 8192);
#pragma unroll
                for (int nt = 0; nt < 4; ++nt)
                    mma16816(acc[mt][nt], ah, bh[nt >> 1][nt & 1], bh[nt >> 1][2 + (nt & 1)]);
#pragma unroll
                for (int nt = 0; nt < 4; ++nt)
                    mma16816(acc[mt][nt], ah, bl[nt >> 1][nt & 1], bl[nt >> 1][2 + (nt & 1)]);
#pragma unroll
                for (int nt = 0; nt < 4; ++nt)
                    mma16816(acc[mt][nt], al, bh[nt >> 1][nt & 1], bh[nt >> 1][2 + (nt & 1)]);
            }
        }
        if (it + 1 < NCH) sts_chunk((it + 1) & 1);
        __syncthreads();
    }

    const int l4 = lane >> 2, l2 = lane & 3;
    const size_t imgbase = (size_t)img * 8 * 2048 * 32;
#pragma unroll
    for (int mt = 0; mt < 4; ++mt) {
        const int co0 = m0 + warp_m * 64 + mt * 16 + l4;
        const float bi0 = bias[co0], bi1 = bias[co0 + 8];
#pragma unroll
        for (int nt = 0; nt < 4; ++nt) {
            const int p = pix0 + warp_n * 32 + nt * 8 + l2 * 2;
            float v0 = acc[mt][nt][0] + bi0;
            float v1 = acc[mt][nt][1] + bi0;
            float v2 = acc[mt][nt][2] + bi1;
            float v3 = acc[mt][nt][3] + bi1;
            const size_t o00 = imgbase + ((size_t)(co0 >> 5) * 2048 + p) * 32 + (co0 & 31);
            const size_t o10 = imgbase + ((size_t)((co0 + 8) >> 5) * 2048 + p) * 32 + ((co0 + 8) & 31);
            __nv_bfloat16 h, l;
            bf16split(v0, h, l); outHi[o00]      = h; outLo[o00]      = l;
            bf16split(v1, h, l); outHi[o00 + 32] = h; outLo[o00 + 32] = l;
            bf16split(v2, h, l); outHi[o10]      = h; outLo[o10]      = l;
            bf16split(v3, h, l); outHi[o10 + 32] = h; outLo[o10 + 32] = l;
        }
    }
}

// =====================================================================
// Shared 512-thread BK=64 conv core constants
// Stage (96KB): A 64KB [hilo][khalf8][co256]x16B at +0,
//               B 32KB [hilo][khalf8][px128]x16B at +65536.
// =====================================================================
#define STG 98304

// conv2 (gen1, polyphase): grid 256 = img*32 + P*16 + htile. 512 thr.
__global__ __launch_bounds__(512, 1)
void conv2_poly(const __nv_bfloat16* __restrict__ Wp,
                const float* __restrict__ bias,
                const __nv_bfloat16* __restrict__ actHi,
                const __nv_bfloat16* __restrict__ actLo,
                __nv_bfloat16* __restrict__ outHi,
                __nv_bfloat16* __restrict__ outLo) {
    extern __shared__ char sm[];
    const int tid  = threadIdx.x;
    const int lane = tid & 31, wid = tid >> 5;
    const int bx   = blockIdx.x;
    const int img  = bx >> 5;
    const int rem  = bx & 31;
    const int P    = rem >> 4;
    const int h0   = (rem & 15) * 4;

    const int NT  = 4 + P;
    const int NCH = NT * 4;
    const uint32_t smem0 = smem_u32(sm);

    auto issue = [&](int it) {
        const uint32_t stage = smem0 + (it & 1) * STG;
        const int tap_t = it % NT, kc2 = it / NT;
        const int tapid = P ? (2 * tap_t) : (2 * tap_t + 1);
        const int dh = tapid / 3 - 1, dw = tapid % 3 - 1;
        // A: 8 coalesced 16B rows
        const __nv_bfloat16* asrc = Wp + ((size_t)(tapid * 4 + kc2)) * 32768 + tid * 8;
#pragma unroll
        for (int i = 0; i < 8; i++)
            cp16(stage + (tid + 512 * i) * 16, asrc + 4096 * i, 16u);
        // B: 4 rows (compact odd-pixel planes)
#pragma unroll
        for (int i = 0; i < 4; i++) {
            const int br = tid + 512 * i;
            const int hilo  = br >> 10;
            const int khalf = (br >> 7) & 7;
            const int px    = br & 127;
            const int row = h0 + (px >> 5);
            const int ow  = 2 * (px & 31) + ((P + row) & 1);
            const int h = row + dh, w = ow + dw;
            const bool ok = ((unsigned)h < 64u) & ((unsigned)w < 64u);
            const int ci = (w - ((h + 1) & 1)) >> 1;
            const int kc = kc2 * 2 + (khalf >> 2);
            const size_t so = ok
                ? (((size_t)(img * 8 + kc) * 2048 + (h * 32 + ci)) * 32 + (khalf & 3) * 8) : 0;
            const __nv_bfloat16* base = hilo ? actLo : actHi;
            cp16(stage + 65536 + br * 16, base + so, ok ? 16u : 0u);
        }
    };

    float acc[4][4][4];
#pragma unroll
    for (int i = 0; i < 4; i++)
#pragma unroll
        for (int j = 0; j < 4; j++)
#pragma unroll
            for (int k = 0; k < 4; k++) acc[i][j][k] = 0.f;

    const int warp_m = wid >> 2;   // 0..3 -> co*64
    const int warp_n = wid & 3;    // 0..3 -> px*32
    const int lrow = (lane & 7) + ((lane >> 3) & 1) * 8;
    const int lkh  = (lane >> 4);

    issue(0); cp_commit();

    for (int it = 0; it < NCH; ++it) {
        if (it + 1 < NCH) issue(it + 1);
        cp_commit();
        cp_wait1();
        __syncthreads();

        const uint32_t S = smem0 + (it & 1) * STG;
#pragma unroll
        for (int k16 = 0; k16 < 4; ++k16) {
            const int khl = k16 * 2 + lkh;
            const uint32_t kbA = S + khl * 4096;
            const uint32_t kbB = S + 65536 + khl * 2048;
            uint32_t bh[2][4], bl[2][4];
#pragma unroll
            for (int ng = 0; ng < 2; ++ng) {
                const uint32_t bd = kbB + (warp_n * 32 + ng * 16 + lrow) * 16;
                ldsm4(bh[ng], bd);
                ldsm4(bl[ng], bd + 16384);
            }
#pragma unroll
            for (int mt = 0; mt < 4; ++mt) {
                uint32_t ah[4], al[4];
                const uint32_t ad = kbA + (warp_m * 64 + mt * 16 + lrow) * 16;
                ldsm4(ah, ad);
                ldsm4(al, ad + 32768);
#pragma unroll
                for (int nt = 0; nt < 4; ++nt)
                    mma16816(acc[mt][nt], ah, bh[nt >> 1][nt & 1], bh[nt >> 1][2 + (nt & 1)]);
#pragma unroll
                for (int nt = 0; nt < 4; ++nt)
                    mma16816(acc[mt][nt], ah, bl[nt >> 1][nt & 1], bl[nt >> 1][2 + (nt & 1)]);
#pragma unroll
                for (int nt = 0; nt < 4; ++nt)
                    mma16816(acc[mt][nt], al, bh[nt >> 1][nt & 1], bh[nt >> 1][2 + (nt & 1)]);
            }
        }
        __syncthreads();
    }

    // epilogue: bias + relu, scatter to dense hi/lo planes
    const int l4 = lane >> 2, l2 = lane & 3;
    const int row = h0 + warp_n;
    const int wpar = (P + row) & 1;
    const size_t imgbase = (size_t)img * 8 * 4096 * 32;
#pragma unroll
    for (int mt = 0; mt < 4; ++mt) {
        const int co0 = warp_m * 64 + mt * 16 + l4;
        const float bi0 = bias[co0], bi1 = bias[co0 + 8];
        const size_t cb0 = imgbase + (size_t)(co0 >> 5) * 4096 * 32 + (co0 & 31);
        const size_t cb1 = imgbase + (size_t)((co0 + 8) >> 5) * 4096 * 32 + ((co0 + 8) & 31);
#pragma unroll
        for (int nt = 0; nt < 4; ++nt) {
            const int j0 = nt * 8 + l2 * 2;
            const int pix0e = row * 64 + 2 * j0 + wpar;
            const int pix1e = pix0e + 2;
            float v0 = fmaxf(acc[mt][nt][0] + bi0, 0.f);
            float v1 = fmaxf(acc[mt][nt][1] + bi0, 0.f);
            float v2 = fmaxf(acc[mt][nt][2] + bi1, 0.f);
            float v3 = fmaxf(acc[mt][nt][3] + bi1, 0.f);
            __nv_bfloat16 h, l;
            bf16split(v0, h, l); outHi[cb0 + (size_t)pix0e * 32] = h; outLo[cb0 + (size_t)pix0e * 32] = l;
            bf16split(v1, h, l); outHi[cb0 + (size_t)pix1e * 32] = h; outLo[cb0 + (size_t)pix1e * 32] = l;
            bf16split(v2, h, l); outHi[cb1 + (size_t)pix0e * 32] = h; outLo[cb1 + (size_t)pix0e * 32] = l;
            bf16split(v3, h, l); outHi[cb1 + (size_t)pix1e * 32] = h; outLo[cb1 + (size_t)pix1e * 32] = l;
        }
    }
}

// conv3 (dense 3x3): grid 256 = img*32 + pixtile. 512 thr, fp32 out.
__global__ __launch_bounds__(512, 1)
void conv3_cp(const __nv_bfloat16* __restrict__ Wp,
              const float* __restrict__ bias,
              const __nv_bfloat16* __restrict__ actHi,
              const __nv_bfloat16* __restrict__ actLo,
              float* __restrict__ outF32) {
    extern __shared__ char sm[];
    const int tid  = threadIdx.x;
    const int lane = tid & 31, wid = tid >> 5;
    const int bx   = blockIdx.x;
    const int img  = bx >> 5;
    const int pix0 = (bx & 31) * 128;
    const int h0   = pix0 >> 6;

    constexpr int NCH = 36;
    const uint32_t smem0 = smem_u32(sm);

    auto issue = [&](int it) {
        const uint32_t stage = smem0 + (it & 1) * STG;
        const int tap = it % 9, kc2 = it / 9;
        const int dh = tap / 3 - 1, dw = tap % 3 - 1;
        const __nv_bfloat16* asrc = Wp + ((size_t)(tap * 4 + kc2)) * 32768 + tid * 8;
#pragma unroll
        for (int i = 0; i < 8; i++)
            cp16(stage + (tid + 512 * i) * 16, asrc + 4096 * i, 16u);
#pragma unroll
        for (int i = 0; i < 4; i++) {
            const int br = tid + 512 * i;
            const int hilo  = br >> 10;
            const int khalf = (br >> 7) & 7;
            const int px    = br & 127;
            const int h = h0 + (px >> 6) + dh, w = (px & 63) + dw;
            const bool ok = ((unsigned)h < 64u) & ((unsigned)w < 64u);
            const int kc = kc2 * 2 + (khalf >> 2);
            const size_t so = ok
                ? (((size_t)(img * 8 + kc) * 4096 + (h * 64 + w)) * 32 + (khalf & 3) * 8) : 0;
            const __nv_bfloat16* base = hilo ? actLo : actHi;
            cp16(stage + 65536 + br * 16, base + so, ok ? 16u : 0u);
        }
    };

    float acc[4][4][4];
#pragma unroll
    for (int i = 0; i < 4; i++)
#pragma unroll
        for (int j = 0; j < 4; j++)
#pragma unroll
            for (int k = 0; k < 4; k++) acc[i][j][k] = 0.f;

    const int warp_m = wid >> 2;
    const int warp_n = wid & 3;
    const int lrow = (lane & 7) + ((lane >> 3) & 1) * 8;
    const int lkh  = (lane >> 4);

    issue(0); cp_commit();

    for (int it = 0; it < NCH; ++it) {
        if (it + 1 < NCH) issue(it + 1);
        cp_commit();
        cp_wait1();
        __syncthreads();

        const uint32_t S = smem0 + (it & 1) * STG;
#pragma unroll
        for (int k16 = 0; k16 < 4; ++k16) {
            const int khl = k16 * 2 + lkh;
            const uint32_t kbA = S + khl * 4096;
            const uint32_t kbB = S + 65536 + khl * 2048;
            uint32_t bh[2][4], bl[2][4];
#pragma unroll
            for (int ng = 0; ng < 2; ++ng) {
                const uint32_t bd = kbB + (warp_n * 32 + ng * 16 + lrow) * 16;
                ldsm4(bh[ng], bd);
                ldsm4(bl[ng], bd + 16384);
            }
#pragma unroll
            for (int mt = 0; mt < 4; ++mt) {
                uint32_t ah[4], al[4];
                const uint32_t ad = kbA + (warp_m * 64 + mt * 16 + lrow) * 16;
                ldsm4(ah, ad);
                ldsm4(al, ad + 32768);
#pragma unroll
                for (int nt = 0; nt < 4; ++nt)
                    mma16816(acc[mt][nt], ah, bh[nt >> 1][nt & 1], bh[nt >> 1][2 + (nt & 1)]);
#pragma unroll
                for (int nt = 0; nt < 4; ++nt)
                    mma16816(acc[mt][nt], ah, bl[nt >> 1][nt & 1], bl[nt >> 1][2 + (nt & 1)]);
#pragma unroll
                for (int nt = 0; nt < 4; ++nt)
                    mma16816(acc[mt][nt], al, bh[nt >> 1][nt & 1], bh[nt >> 1][2 + (nt & 1)]);
            }
        }
        __syncthreads();
    }

    const int l4 = lane >> 2, l2 = lane & 3;
    float* outImg = outF32 + (size_t)img * CT * PIX;
#pragma unroll
    for (int mt = 0; mt < 4; ++mt) {
        const int co0 = warp_m * 64 + mt * 16 + l4;
        const float bi0 = bias[co0], bi1 = bias[co0 + 8];
#pragma unroll
        for (int nt = 0; nt < 4; ++nt) {
            const int p = pix0 + warp_n * 32 + nt * 8 + l2 * 2;
            float v0 = acc[mt][nt][0] + bi0;
            float v1 = acc[mt][nt][1] + bi0;
            float v2 = acc[mt][nt][2] + bi1;
            float v3 = acc[mt][nt][3] + bi1;
            *(float2*)(outImg + (size_t)co0 * PIX + p)       = make_float2(v0, v1);
            *(float2*)(outImg + (size_t)(co0 + 8) * PIX + p) = make_float2(v2, v3);
        }
    }
}

// =====================================================================
// pairwise dots + target norms (unchanged, verified)
// =====================================================================
__global__ __launch_bounds__(256)
void dot_kernel(const float* __restrict__ p, const float* __restrict__ t) {
    const int tid = threadIdx.x;
    const int d0  = blockIdx.x * 2048 + tid;

    float dacc[8][8];
    float tn[8];
#pragma unroll
    for (int i = 0; i < 8; i++) {
        tn[i] = 0.f;
#pragma unroll
        for (int j = 0; j < 8; j++) dacc[i][j] = 0.f;
    }
#pragma unroll 2
    for (int it = 0; it < 8; it++) {
        int d = d0 + it * 256;
        float pv[8], tv[8];
#pragma unroll
        for (int i = 0; i < 8; i++) {
            pv[i] = __ldg(p + (size_t)i * DTOT + d);
            tv[i] = __ldg(t + (size_t)i * DTOT + d);
        }
#pragma unroll
        for (int j = 0; j < 8; j++) tn[j] = fmaf(tv[j], tv[j], tn[j]);
#pragma unroll
        for (int i = 0; i < 8; i++)
#pragma unroll
            for (int j = 0; j < 8; j++)
                dacc[i][j] = fmaf(pv[i], tv[j], dacc[i][j]);
    }
    __shared__ float red[8][72];
    const int lane = tid & 31, warp = tid >> 5;
#pragma unroll
    for (int i = 0; i < 8; i++)
#pragma unroll
        for (int j = 0; j < 8; j++) {
            float v = dacc[i][j];
#pragma unroll
            for (int s = 16; s; s >>= 1) v += __shfl_xor_sync(0xFFFFFFFFu, v, s);
            if (lane == 0) red[warp][i*8+j] = v;
        }
#pragma unroll
    for (int j = 0; j < 8; j++) {
        float v = tn[j];
#pragma unroll
        for (int s = 16; s; s >>= 1) v += __shfl_xor_sync(0xFFFFFFFFu, v, s);
        if (lane == 0) red[warp][64+j] = v;
    }
    __syncthreads();
    if (tid < 72) {
        double s = 0.0;
#pragma unroll
        for (int w = 0; w < 8; w++) s += (double)red[w][tid];
        atomicAdd(&g_acc[tid], s);
    }
}

__global__ void finalize_kernel(float* __restrict__ out) {
    if (threadIdx.x != 0 || blockIdx.x != 0) return;
    double L[8][8];
    for (int i = 0; i < 8; i++)
        for (int j = 0; j < 8; j++)
            L[i][j] = (g_acc[i*8+j] - 0.5 * g_acc[64+j]) / 64.0;
    double ce = 0.0;
    for (int i = 0; i < 8; i++) {
        double m = L[i][0];
        for (int j = 1; j < 8; j++) m = L[i][j] > m ? L[i][j] : m;
        double s = 0.0;
        for (int j = 0; j < 8; j++) s += exp(L[i][j] - m);
        ce += (m + log(s)) - L[i][i];
    }
    ce /= 8.0;
    double loss = ce * (2.0 * 64.0 / 8.0) * 2e-05;
    out[0] = (float)loss;
}

// =====================================================================
extern "C" void kernel_launch(void* const* d_in, const int* in_sizes, int n_in,
                              void* d_out, int out_size) {
    const float* S  = (const float*)d_in[0];
    const float* T  = (const float*)d_in[1];
    const float* Wa = (const float*)d_in[2];
    const float* ba = (const float*)d_in[3];
    const float* W1 = (const float*)d_in[4];
    const float* b1 = (const float*)d_in[5];
    const float* W2 = (const float*)d_in[6];
    const float* b2 = (const float*)d_in[7];
    float* out = (float*)d_out;

    float* tbuf;
    cudaGetSymbolAddress((void**)&tbuf, g_t);
    __nv_bfloat16 *waH, *waL, *w1p, *w2p, *mHi, *mLo, *g1Hi, *g1Lo;
    cudaGetSymbolAddress((void**)&waH, g_WaHi);
    cudaGetSymbolAddress((void**)&waL, g_WaLo);
    cudaGetSymbolAddress((void**)&w1p, g_W1p);
    cudaGetSymbolAddress((void**)&w2p, g_W2p);
    cudaGetSymbolAddress((void**)&mHi, g_mHi);
    cudaGetSymbolAddress((void**)&mLo, g_mLo);
    cudaGetSymbolAddress((void**)&g1Hi, g_g1Hi);
    cudaGetSymbolAddress((void**)&g1Lo, g_g1Lo);

    cudaFuncSetAttribute(conv1_mma,  cudaFuncAttributeMaxDynamicSharedMemorySize, 65536);
    cudaFuncSetAttribute(conv2_poly, cudaFuncAttributeMaxDynamicSharedMemorySize, 2 * STG);
    cudaFuncSetAttribute(conv3_cp,   cudaFuncAttributeMaxDynamicSharedMemorySize, 2 * STG);

    init_kernel<<<1, 128>>>();
    {
        int total = 256*128 + 36*32768;
        wprep_kernel<<<(total + 255) / 256, 256>>>(Wa, W1, W2);
    }
    conv1_mma <<<dim3(128, 2), 256, 65536>>>(waH, waL, ba, S, mHi, mLo);
    conv2_poly<<<256, 512, 2 * STG>>>(w1p, b1, mHi, mLo, g1Hi, g1Lo);
    conv3_cp  <<<256, 512, 2 * STG>>>(w2p, b2, g1Hi, g1Lo, tbuf);

    dot_kernel<<<DTOT / 2048, 256>>>(T, tbuf);
    finalize_kernel<<<1, 1>>>(out);
}

// round 9
// speedup vs baseline: 3.2761x; 1.0250x over previous
#include <cuda_runtime.h>
#include <cuda_bf16.h>
#include <cstdint>
#include <math.h>

#define NIMG 8
#define CS   128
#define CT   256
#define PIX  4096           // 64*64
#define DTOT (CT*PIX)       // per image

// ---- scratch (__device__ globals; no allocation allowed) ----
__device__ float g_t[(size_t)NIMG*CT*PIX];
__device__ double g_acc[72];

// conv1 output: COMPACT odd-parity pixels only, [img][kc(8)][pix2048][32ch]
__device__ __align__(16) __nv_bfloat16 g_mHi[(size_t)NIMG*8*2048*32];
__device__ __align__(16) __nv_bfloat16 g_mLo[(size_t)NIMG*8*2048*32];
// gen1 output: dense [img][kc(8)][pix4096][32ch]
__device__ __align__(16) __nv_bfloat16 g_g1Hi[(size_t)NIMG*8*4096*32];
__device__ __align__(16) __nv_bfloat16 g_g1Lo[(size_t)NIMG*8*4096*32];

// conv1 weights (row-major hi/lo)
__device__ __align__(16) __nv_bfloat16 g_WaHi[256*128], g_WaLo[256*128];
// conv2/3 weights packed for 512-thread BK=64 stages:
// chunk = tap*4 + kc2 (36 chunks); within 32768 elems: r(0..4095)*8 + j
// r = hilo*2048 + khalf*256 + co
__device__ __align__(16) __nv_bfloat16 g_W1p[36*32768];
__device__ __align__(16) __nv_bfloat16 g_W2p[36*32768];

// =====================================================================
// helpers (sm_80+ baseline PTX)
// =====================================================================
__device__ __forceinline__ uint32_t smem_u32(const void* p) {
    uint32_t a;
    asm("{ .reg .u64 t; cvta.to.shared.u64 t, %1; cvt.u32.u64 %0, t; }" : "=r"(a) : "l"(p));
    return a;
}
__device__ __forceinline__ void ldsm4(uint32_t* r, uint32_t addr) {
    asm volatile("ldmatrix.sync.aligned.m8n8.x4.shared.b16 {%0,%1,%2,%3}, [%4];"
                 : "=r"(r[0]), "=r"(r[1]), "=r"(r[2]), "=r"(r[3]) : "r"(addr));
}
__device__ __forceinline__ void mma16816(float* c, const uint32_t* a, uint32_t b0, uint32_t b1) {
    asm volatile("mma.sync.aligned.m16n8k16.row.col.f32.bf16.bf16.f32 "
                 "{%0,%1,%2,%3}, {%4,%5,%6,%7}, {%8,%9}, {%0,%1,%2,%3};"
                 : "+f"(c[0]), "+f"(c[1]), "+f"(c[2]), "+f"(c[3])
                 : "r"(a[0]), "r"(a[1]), "r"(a[2]), "r"(a[3]), "r"(b0), "r"(b1));
}
__device__ __forceinline__ void cp16(uint32_t dst, const void* src, uint32_t sz) {
    asm volatile("cp.async.cg.shared.global [%0], [%1], 16, %2;"
                 :: "r"(dst), "l"(src), "r"(sz) : "memory");
}
__device__ __forceinline__ void cp_commit() {
    asm volatile("cp.async.commit_group;" ::: "memory");
}
__device__ __forceinline__ void cp_wait1() {
    asm volatile("cp.async.wait_group 1;" ::: "memory");
}
__device__ __forceinline__ void bf16split(float v, __nv_bfloat16& h, __nv_bfloat16& l) {
    h = __float2bfloat16(v);
    l = __float2bfloat16(v - __bfloat162float(h));
}

// =====================================================================
// Weight prep (512-thread BK=64 packing, chunk = tap*4 + kc2)
// =====================================================================
__global__ void wprep_kernel(const float* __restrict__ Wa, const float* __restrict__ W1,
                             const float* __restrict__ W2) {
    int t = blockIdx.x * blockDim.x + threadIdx.x;
    if (t < 256*128) {
        float v = Wa[t];
        __nv_bfloat16 h, l;
        bf16split(v, h, l);
        g_WaHi[t] = h; g_WaLo[t] = l;
    }
    int u = t - 256*128;
    if (u >= 0 && u < 36*32768) {
        int chunk  = u >> 15;
        int within = u & 32767;
        int r = within >> 3, j = within & 7;
        int tap = chunk >> 2;
        int kc2 = chunk & 3;
        int hilo  = r >> 11;
        int khalf = (r >> 8) & 7;
        int co    = r & 255;
        int ci    = kc2 * 64 + khalf * 8 + j;
        int src   = co * 2304 + ci * 9 + tap;
        {
            __nv_bfloat16 h, l;
            bf16split(W1[src], h, l);
            g_W1p[u] = hilo ? l : h;
        }
        {
            __nv_bfloat16 h, l;
            bf16split(W2[src], h, l);
            g_W2p[u] = hilo ? l : h;
        }
    }
}

__global__ void init_kernel() {
    if (threadIdx.x < 72) g_acc[threadIdx.x] = 0.0;
}

// =====================================================================
// conv1 (1x1, K=128): odd-parity pixels only (verified).
// =====================================================================
__global__ __launch_bounds__(256, 2)
void conv1_mma(const __nv_bfloat16* __restrict__ Whi, const __nv_bfloat16* __restrict__ Wlo,
               const float* __restrict__ bias, const float* __restrict__ in,
               __nv_bfloat16* __restrict__ outHi, __nv_bfloat16* __restrict__ outLo) {
    extern __shared__ char sm[];
    const int tid  = threadIdx.x;
    const int lane = tid & 31, wid = tid >> 5;
    const int m0   = blockIdx.y * 128;
    const int bx   = blockIdx.x;
    const int img  = bx >> 4;
    const int pix0 = (bx & 15) * 128;
    const float* inImg = in + (size_t)img * CS * PIX;

    constexpr int NCH = CS / 32;  // 4

    const int a_row = tid >> 1;
    const int a_k0  = (tid & 1) * 16;
    const int b_n   = tid & 127;
    const int b_sg  = tid >> 7;
    const int cpx  = pix0 + b_n;
    const int ch_h = cpx >> 5;
    const int ch_w = 2 * (cpx & 31) + ((ch_h + 1) & 1);
    const int bsrc = ch_h * 64 + ch_w;

    uint4 rAh[2], rAl[2];
    float rB[16];

    auto ldg_chunk = [&](int it) {
        const int c0 = it * 32;
        size_t aoff = (size_t)(m0 + a_row) * CS + c0 + a_k0;
        rAh[0] = *(const uint4*)(Whi + aoff);
        rAh[1] = *(const uint4*)(Whi + aoff + 8);
        rAl[0] = *(const uint4*)(Wlo + aoff);
        rAl[1] = *(const uint4*)(Wlo + aoff + 8);
        const float* p = inImg + (size_t)(c0 + b_sg * 16) * PIX + bsrc;
#pragma unroll
        for (int q = 0; q < 16; q++)
            rB[q] = __ldg(p + (size_t)q * PIX);
    };

    auto sts_chunk = [&](int s) {
        char* Ahi = sm + s * 32768;
        char* Alo = Ahi + 8192;
        char* Bhi = Ahi + 16384;
        char* Blo = Ahi + 24576;
        const int kh0 = a_k0 >> 3;
        *(uint4*)(Ahi + (kh0    ) * 2048 + a_row * 16) = rAh[0];
        *(uint4*)(Ahi + (kh0 + 1) * 2048 + a_row * 16) = rAh[1];
        *(uint4*)(Alo + (kh0    ) * 2048 + a_row * 16) = rAl[0];
        *(uint4*)(Alo + (kh0 + 1) * 2048 + a_row * 16) = rAl[1];
#pragma unroll
        for (int g = 0; g < 2; g++) {
            uint32_t hp[4], lp[4];
#pragma unroll
            for (int jp = 0; jp < 4; jp++) {
                float x0 = rB[g * 8 + 2 * jp], x1 = rB[g * 8 + 2 * jp + 1];
                __nv_bfloat16 hb0, lb0, hb1, lb1;
                bf16split(x0, hb0, lb0);
                bf16split(x1, hb1, lb1);
                hp[jp] = (uint32_t)__bfloat16_as_ushort(hb0)
                       | ((uint32_t)__bfloat16_as_ushort(hb1) << 16);
                lp[jp] = (uint32_t)__bfloat16_as_ushort(lb0)
                       | ((uint32_t)__bfloat16_as_ushort(lb1) << 16);
            }
            const int kh = b_sg * 2 + g;
            *(uint4*)(Bhi + kh * 2048 + b_n * 16) = make_uint4(hp[0], hp[1], hp[2], hp[3]);
            *(uint4*)(Blo + kh * 2048 + b_n * 16) = make_uint4(lp[0], lp[1], lp[2], lp[3]);
        }
    };

    float acc[4][4][4];
#pragma unroll
    for (int i = 0; i < 4; i++)
#pragma unroll
        for (int j = 0; j < 4; j++)
#pragma unroll
            for (int k = 0; k < 4; k++) acc[i][j][k] = 0.f;

    const int warp_m = wid & 1;
    const int warp_n = wid >> 1;
    const uint32_t smem0 = smem_u32(sm);
    const int lrow = (lane & 7) + ((lane >> 3) & 1) * 8;
    const int lkh  = (lane >> 4);

    ldg_chunk(0);
    sts_chunk(0);
    __syncthreads();

    for (int it = 0; it < NCH; ++it) {
        if (it + 1 < NCH) ldg_chunk(it + 1);
        const uint32_t S = smem0 + (it & 1) * 32768;
#pragma unroll
        for (int k16 = 0; k16 < 2; ++k16) {
            const uint32_t kbase = S + (k16 * 2 + lkh) * 2048;
            uint32_t bh[2][4], bl[2][4];
#pragma unroll
            for (int ng = 0; ng < 2; ++ng) {
                const uint32_t bd = kbase + 16384 + (warp_n * 32 + ng * 16 + lrow) * 16;
                ldsm4(bh[ng], bd);
                ldsm4(bl[ng], bd + 8192);
            }
#pragma unroll
            for (int mt = 0; mt < 4; ++mt) {
                uint32_t ah[4], al[4];
                const uint32_t ad = kbase + (warp_m * 64 + mt * 16 + lrow) * 16;
                ldsm4(ah, ad);
                ldsm4(al, ad + 8192);
#pragma unroll
                for (int nt = 0; nt < 4; ++nt)
                    mma16816(acc[mt][nt], ah, bh[nt >> 1][nt & 1], bh[nt >> 1][2 + (nt & 1)]);
#pragma unroll
                for (int nt = 0; nt < 4; ++nt)
                    mma16816(acc[mt][nt], ah, bl[nt >> 1][nt & 1], bl[nt >> 1][2 + (nt & 1)]);
#pragma unroll
                for (int nt = 0; nt < 4; ++nt)
                    mma16816(acc[mt][nt], al, bh[nt >> 1][nt & 1], bh[nt >> 1][2 + (nt & 1)]);
            }
        }
        if (it + 1 < NCH) sts_chunk((it + 1) & 1);
        __syncthreads();
    }

    const int l4 = lane >> 2, l2 = lane & 3;
    const size_t imgbase = (size_t)img * 8 * 2048 * 32;
#pragma unroll
    for (int mt = 0; mt < 4; ++mt) {
        const int co0 = m0 + warp_m * 64 + mt * 16 + l4;
        const float bi0 = bias[co0], bi1 = bias[co0 + 8];
#pragma unroll
        for (int nt = 0; nt < 4; ++nt) {
            const int p = pix0 + warp_n * 32 + nt * 8 + l2 * 2;
            float v0 = acc[mt][nt][0] + bi0;
            float v1 = acc[mt][nt][1] + bi0;
            float v2 = acc[mt][nt][2] + bi1;
            float v3 = acc[mt][nt][3] + bi1;
            const size_t o00 = imgbase + ((size_t)(co0 >> 5) * 2048 + p) * 32 + (co0 & 31);
            const size_t o10 = imgbase + ((size_t)((co0 + 8) >> 5) * 2048 + p) * 32 + ((co0 + 8) & 31);
            __nv_bfloat16 h, l;
            bf16split(v0, h, l); outHi[o00]      = h; outLo[o00]      = l;
            bf16split(v1, h, l); outHi[o00 + 32] = h; outLo[o00 + 32] = l;
            bf16split(v2, h, l); outHi[o10]      = h; outLo[o10]      = l;
            bf16split(v3, h, l); outHi[o10 + 32] = h; outLo[o10 + 32] = l;
        }
    }
}

// =====================================================================
// Shared 512-thread BK=64 conv core
// Stage (96KB): A 64KB at +0, B 32KB at +65536.
// Producer state: per-tap geometry hoisted; steady issue is linear.
// =====================================================================
#define STG 98304

// conv2 (gen1, polyphase): grid 256 = img*32 + P*16 + htile. 512 thr.
// Chunk order: tap-outer, kc2-inner (it = tap_t*4 + kc2).
__global__ __launch_bounds__(512, 1)
void conv2_poly(const __nv_bfloat16* __restrict__ Wp,
                const float* __restrict__ bias,
                const __nv_bfloat16* __restrict__ actHi,
                const __nv_bfloat16* __restrict__ actLo,
                __nv_bfloat16* __restrict__ outHi,
                __nv_bfloat16* __restrict__ outLo) {
    extern __shared__ char sm[];
    const int tid  = threadIdx.x;
    const int lane = tid & 31, wid = tid >> 5;
    const int bx   = blockIdx.x;
    const int img  = bx >> 5;
    const int rem  = bx & 31;
    const int P    = rem >> 4;
    const int h0   = (rem & 15) * 4;

    const int NT  = 4 + P;
    const int NCH = NT * 4;
    const uint32_t smem0 = smem_u32(sm);
    const uint32_t dstA0 = smem0 + tid * 16;
    const uint32_t dstB0 = smem0 + 65536 + tid * 16;

    // producer rolling state
    const __nv_bfloat16* aPtr = Wp + tid * 8;  // rebased per tap
    uint32_t bOff[2];
    uint32_t bOk = 0;

    auto setup_tap = [&](int tap_t) {
        const int tapid = P ? (2 * tap_t) : (2 * tap_t + 1);
        const int dh = tapid / 3 - 1, dw = tapid % 3 - 1;
        aPtr = Wp + (size_t)tapid * 4 * 32768 + tid * 8;
        bOk = 0;
#pragma unroll
        for (int r = 0; r < 2; ++r) {
            const int br = tid + 512 * r;
            const int khalf = (br >> 7) & 7;
            const int px    = br & 127;
            const int row = h0 + (px >> 5);
            const int ow  = 2 * (px & 31) + ((P + row) & 1);
            const int h = row + dh, w = ow + dw;
            const bool ok = ((unsigned)h < 64u) & ((unsigned)w < 64u);
            const int ci = ok ? ((w - ((h + 1) & 1)) >> 1) : 0;
            const int hpix = ok ? (h * 32 + ci) : 0;
            bOff[r] = ((uint32_t)(img * 8 + (khalf >> 2)) * 2048 + hpix) * 32 + (khalf & 3) * 8;
            bOk |= (ok ? 1u : 0u) << r;
        }
    };

    auto issue = [&](int it) {
        const uint32_t sb = (uint32_t)(it & 1) * STG;
        const int kc2 = it & 3;
        if (kc2 == 0) setup_tap(it >> 2);
        const __nv_bfloat16* a = aPtr + kc2 * 32768;
#pragma unroll
        for (int i = 0; i < 8; i++)
            cp16(dstA0 + sb + 8192u * i, a + 4096 * i, 16u);
        const uint32_t kadd = (uint32_t)kc2 * 131072u;  // 2*2048*32 elems
        const uint32_t s0 = (bOk & 1u) ? 16u : 0u;
        const uint32_t s1 = (bOk & 2u) ? 16u : 0u;
        cp16(dstB0 + sb,         actHi + bOff[0] + kadd, s0);
        cp16(dstB0 + sb + 8192,  actHi + bOff[1] + kadd, s1);
        cp16(dstB0 + sb + 16384, actLo + bOff[0] + kadd, s0);
        cp16(dstB0 + sb + 24576, actLo + bOff[1] + kadd, s1);
    };

    float acc[4][4][4];
#pragma unroll
    for (int i = 0; i < 4; i++)
#pragma unroll
        for (int j = 0; j < 4; j++)
#pragma unroll
            for (int k = 0; k < 4; k++) acc[i][j][k] = 0.f;

    const int warp_m = wid >> 2;
    const int warp_n = wid & 3;
    const int lrow = (lane & 7) + ((lane >> 3) & 1) * 8;
    const int lkh  = (lane >> 4);

    issue(0); cp_commit();

    for (int it = 0; it < NCH; ++it) {
        if (it + 1 < NCH) issue(it + 1);
        cp_commit();
        cp_wait1();
        __syncthreads();

        const uint32_t S = smem0 + (it & 1) * STG;
#pragma unroll
        for (int k16 = 0; k16 < 4; ++k16) {
            const int khl = k16 * 2 + lkh;
            const uint32_t kbA = S + khl * 4096;
            const uint32_t kbB = S + 65536 + khl * 2048;
            uint32_t bh[2][4], bl[2][4];
#pragma unroll
            for (int ng = 0; ng < 2; ++ng) {
                const uint32_t bd = kbB + (warp_n * 32 + ng * 16 + lrow) * 16;
                ldsm4(bh[ng], bd);
                ldsm4(bl[ng], bd + 16384);
            }
#pragma unroll
            for (int mt = 0; mt < 4; ++mt) {
                uint32_t ah[4], al[4];
                const uint32_t ad = kbA + (warp_m * 64 + mt * 16 + lrow) * 16;
                ldsm4(ah, ad);
                ldsm4(al, ad + 32768);
#pragma unroll
                for (int nt = 0; nt < 4; ++nt)
                    mma16816(acc[mt][nt], ah, bh[nt >> 1][nt & 1], bh[nt >> 1][2 + (nt & 1)]);
#pragma unroll
                for (int nt = 0; nt < 4; ++nt)
                    mma16816(acc[mt][nt], ah, bl[nt >> 1][nt & 1], bl[nt >> 1][2 + (nt & 1)]);
#pragma unroll
                for (int nt = 0; nt < 4; ++nt)
                    mma16816(acc[mt][nt], al, bh[nt >> 1][nt & 1], bh[nt >> 1][2 + (nt & 1)]);
            }
        }
        __syncthreads();
    }

    // epilogue: bias + relu, scatter to dense hi/lo planes
    const int l4 = lane >> 2, l2 = lane & 3;
    const int row = h0 + warp_n;
    const int wpar = (P + row) & 1;
    const size_t imgbase = (size_t)img * 8 * 4096 * 32;
#pragma unroll
    for (int mt = 0; mt < 4; ++mt) {
        const int co0 = warp_m * 64 + mt * 16 + l4;
        const float bi0 = bias[co0], bi1 = bias[co0 + 8];
        const size_t cb0 = imgbase + (size_t)(co0 >> 5) * 4096 * 32 + (co0 & 31);
        const size_t cb1 = imgbase + (size_t)((co0 + 8) >> 5) * 4096 * 32 + ((co0 + 8) & 31);
#pragma unroll
        for (int nt = 0; nt < 4; ++nt) {
            const int j0 = nt * 8 + l2 * 2;
            const int pix0e = row * 64 + 2 * j0 + wpar;
            const int pix1e = pix0e + 2;
            float v0 = fmaxf(acc[mt][nt][0] + bi0, 0.f);
            float v1 = fmaxf(acc[mt][nt][1] + bi0, 0.f);
            float v2 = fmaxf(acc[mt][nt][2] + bi1, 0.f);
            float v3 = fmaxf(acc[mt][nt][3] + bi1, 0.f);
            __nv_bfloat16 h, l;
            bf16split(v0, h, l); outHi[cb0 + (size_t)pix0e * 32] = h; outLo[cb0 + (size_t)pix0e * 32] = l;
            bf16split(v1, h, l); outHi[cb0 + (size_t)pix1e * 32] = h; outLo[cb0 + (size_t)pix1e * 32] = l;
            bf16split(v2, h, l); outHi[cb1 + (size_t)pix0e * 32] = h; outLo[cb1 + (size_t)pix0e * 32] = l;
            bf16split(v3, h, l); outHi[cb1 + (size_t)pix1e * 32] = h; outLo[cb1 + (size_t)pix1e * 32] = l;
        }
    }
}

// conv3 (dense 3x3): grid 256 = img*32 + pixtile. 512 thr, fp32 out.
__global__ __launch_bounds__(512, 1)
void conv3_cp(const __nv_bfloat16* __restrict__ Wp,
              const float* __restrict__ bias,
              const __nv_bfloat16* __restrict__ actHi,
              const __nv_bfloat16* __restrict__ actLo,
              float* __restrict__ outF32) {
    extern __shared__ char sm[];
    const int tid  = threadIdx.x;
    const int lane = tid & 31, wid = tid >> 5;
    const int bx   = blockIdx.x;
    const int img  = bx >> 5;
    const int pix0 = (bx & 31) * 128;
    const int h0   = pix0 >> 6;

    constexpr int NCH = 36;
    const uint32_t smem0 = smem_u32(sm);
    const uint32_t dstA0 = smem0 + tid * 16;
    const uint32_t dstB0 = smem0 + 65536 + tid * 16;

    const __nv_bfloat16* aPtr = Wp + tid * 8;
    uint32_t bOff[2];
    uint32_t bOk = 0;

    auto setup_tap = [&](int tap) {
        const int dh = tap / 3 - 1, dw = tap % 3 - 1;
        aPtr = Wp + (size_t)tap * 4 * 32768 + tid * 8;
        bOk = 0;
#pragma unroll
        for (int r = 0; r < 2; ++r) {
            const int br = tid + 512 * r;
            const int khalf = (br >> 7) & 7;
            const int px    = br & 127;
            const int h = h0 + (px >> 6) + dh, w = (px & 63) + dw;
            const bool ok = ((unsigned)h < 64u) & ((unsigned)w < 64u);
            const int hpix = ok ? (h * 64 + w) : 0;
            bOff[r] = ((uint32_t)(img * 8 + (khalf >> 2)) * 4096 + hpix) * 32 + (khalf & 3) * 8;
            bOk |= (ok ? 1u : 0u) << r;
        }
    };

    auto issue = [&](int it) {
        const uint32_t sb = (uint32_t)(it & 1) * STG;
        const int kc2 = it & 3;
        if (kc2 == 0) setup_tap(it >> 2);
        const __nv_bfloat16* a = aPtr + kc2 * 32768;
#pragma unroll
        for (int i = 0; i < 8; i++)
            cp16(dstA0 + sb + 8192u * i, a + 4096 * i, 16u);
        const uint32_t kadd = (uint32_t)kc2 * 262144u;  // 2*4096*32 elems
        const uint32_t s0 = (bOk & 1u) ? 16u : 0u;
        const uint32_t s1 = (bOk & 2u) ? 16u : 0u;
        cp16(dstB0 + sb,         actHi + bOff[0] + kadd, s0);
        cp16(dstB0 + sb + 8192,  actHi + bOff[1] + kadd, s1);
        cp16(dstB0 + sb + 16384, actLo + bOff[0] + kadd, s0);
        cp16(dstB0 + sb + 24576, actLo + bOff[1] + kadd, s1);
    };

    float acc[4][4][4];
#pragma unroll
    for (int i = 0; i < 4; i++)
#pragma unroll
        for (int j = 0; j < 4; j++)
#pragma unroll
            for (int k = 0; k < 4; k++) acc[i][j][k] = 0.f;

    const int warp_m = wid >> 2;
    const int warp_n = wid & 3;
    const int lrow = (lane & 7) + ((lane >> 3) & 1) * 8;
    const int lkh  = (lane >> 4);

    issue(0); cp_commit();

    for (int it = 0; it < NCH; ++it) {
        if (it + 1 < NCH) issue(it + 1);
        cp_commit();
        cp_wait1();
        __syncthreads();

        const uint32_t S = smem0 + (it & 1) * STG;
#pragma unroll
        for (int k16 = 0; k16 < 4; ++k16) {
            const int khl = k16 * 2 + lkh;
            const uint32_t kbA = S + khl * 4096;
            const uint32_t kbB = S + 65536 + khl * 2048;
            uint32_t bh[2][4], bl[2][4];
#pragma unroll
            for (int ng = 0; ng < 2; ++ng) {
                const uint32_t bd = kbB + (warp_n * 32 + ng * 16 + lrow) * 16;
                ldsm4(bh[ng], bd);
                ldsm4(bl[ng], bd + 16384);
            }
#pragma unroll
            for (int mt = 0; mt < 4; ++mt) {
                uint32_t ah[4], al[4];
                const uint32_t ad = kbA + (warp_m * 64 + mt * 16 + lrow) * 16;
                ldsm4(ah, ad);
                ldsm4(al, ad + 32768);
#pragma unroll
                for (int nt = 0; nt < 4; ++nt)
                    mma16816(acc[mt][nt], ah, bh[nt >> 1][nt & 1], bh[nt >> 1][2 + (nt & 1)]);
#pragma unroll
                for (int nt = 0; nt < 4; ++nt)
                    mma16816(acc[mt][nt], ah, bl[nt >> 1][nt & 1], bl[nt >> 1][2 + (nt & 1)]);
#pragma unroll
                for (int nt = 0; nt < 4; ++nt)
                    mma16816(acc[mt][nt], al, bh[nt >> 1][nt & 1], bh[nt >> 1][2 + (nt & 1)]);
            }
        }
        __syncthreads();
    }

    const int l4 = lane >> 2, l2 = lane & 3;
    float* outImg = outF32 + (size_t)img * CT * PIX;
#pragma unroll
    for (int mt = 0; mt < 4; ++mt) {
        const int co0 = warp_m * 64 + mt * 16 + l4;
        const float bi0 = bias[co0], bi1 = bias[co0 + 8];
#pragma unroll
        for (int nt = 0; nt < 4; ++nt) {
            const int p = pix0 + warp_n * 32 + nt * 8 + l2 * 2;
            float v0 = acc[mt][nt][0] + bi0;
            float v1 = acc[mt][nt][1] + bi0;
            float v2 = acc[mt][nt][2] + bi1;
            float v3 = acc[mt][nt][3] + bi1;
            *(float2*)(outImg + (size_t)co0 * PIX + p)       = make_float2(v0, v1);
            *(float2*)(outImg + (size_t)(co0 + 8) * PIX + p) = make_float2(v2, v3);
        }
    }
}

// =====================================================================
// pairwise dots + target norms (unchanged, verified)
// =====================================================================
__global__ __launch_bounds__(256)
void dot_kernel(const float* __restrict__ p, const float* __restrict__ t) {
    const int tid = threadIdx.x;
    const int d0  = blockIdx.x * 2048 + tid;

    float dacc[8][8];
    float tn[8];
#pragma unroll
    for (int i = 0; i < 8; i++) {
        tn[i] = 0.f;
#pragma unroll
        for (int j = 0; j < 8; j++) dacc[i][j] = 0.f;
    }
#pragma unroll 2
    for (int it = 0; it < 8; it++) {
        int d = d0 + it * 256;
        float pv[8], tv[8];
#pragma unroll
        for (int i = 0; i < 8; i++) {
            pv[i] = __ldg(p + (size_t)i * DTOT + d);
            tv[i] = __ldg(t + (size_t)i * DTOT + d);
        }
#pragma unroll
        for (int j = 0; j < 8; j++) tn[j] = fmaf(tv[j], tv[j], tn[j]);
#pragma unroll
        for (int i = 0; i < 8; i++)
#pragma unroll
            for (int j = 0; j < 8; j++)
                dacc[i][j] = fmaf(pv[i], tv[j], dacc[i][j]);
    }
    __shared__ float red[8][72];
    const int lane = tid & 31, warp = tid >> 5;
#pragma unroll
    for (int i = 0; i < 8; i++)
#pragma unroll
        for (int j = 0; j < 8; j++) {
            float v = dacc[i][j];
#pragma unroll
            for (int s = 16; s; s >>= 1) v += __shfl_xor_sync(0xFFFFFFFFu, v, s);
            if (lane == 0) red[warp][i*8+j] = v;
        }
#pragma unroll
    for (int j = 0; j < 8; j++) {
        float v = tn[j];
#pragma unroll
        for (int s = 16; s; s >>= 1) v += __shfl_xor_sync(0xFFFFFFFFu, v, s);
        if (lane == 0) red[warp][64+j] = v;
    }
    __syncthreads();
    if (tid < 72) {
        double s = 0.0;
#pragma unroll
        for (int w = 0; w < 8; w++) s += (double)red[w][tid];
        atomicAdd(&g_acc[tid], s);
    }
}

__global__ void finalize_kernel(float* __restrict__ out) {
    if (threadIdx.x != 0 || blockIdx.x != 0) return;
    double L[8][8];
    for (int i = 0; i < 8; i++)
        for (int j = 0; j < 8; j++)
            L[i][j] = (g_acc[i*8+j] - 0.5 * g_acc[64+j]) / 64.0;
    double ce = 0.0;
    for (int i = 0; i < 8; i++) {
        double m = L[i][0];
        for (int j = 1; j < 8; j++) m = L[i][j] > m ? L[i][j] : m;
        double s = 0.0;
        for (int j = 0; j < 8; j++) s += exp(L[i][j] - m);
        ce += (m + log(s)) - L[i][i];
    }
    ce /= 8.0;
    double loss = ce * (2.0 * 64.0 / 8.0) * 2e-05;
    out[0] = (float)loss;
}

// =====================================================================
extern "C" void kernel_launch(void* const* d_in, const int* in_sizes, int n_in,
                              void* d_out, int out_size) {
    const float* S  = (const float*)d_in[0];
    const float* T  = (const float*)d_in[1];
    const float* Wa = (const float*)d_in[2];
    const float* ba = (const float*)d_in[3];
    const float* W1 = (const float*)d_in[4];
    const float* b1 = (const float*)d_in[5];
    const float* W2 = (const float*)d_in[6];
    const float* b2 = (const float*)d_in[7];
    float* out = (float*)d_out;

    float* tbuf;
    cudaGetSymbolAddress((void**)&tbuf, g_t);
    __nv_bfloat16 *waH, *waL, *w1p, *w2p, *mHi, *mLo, *g1Hi, *g1Lo;
    cudaGetSymbolAddress((void**)&waH, g_WaHi);
    cudaGetSymbolAddress((void**)&waL, g_WaLo);
    cudaGetSymbolAddress((void**)&w1p, g_W1p);
    cudaGetSymbolAddress((void**)&w2p, g_W2p);
    cudaGetSymbolAddress((void**)&mHi, g_mHi);
    cudaGetSymbolAddress((void**)&mLo, g_mLo);
    cudaGetSymbolAddress((void**)&g1Hi, g_g1Hi);
    cudaGetSymbolAddress((void**)&g1Lo, g_g1Lo);

    cudaFuncSetAttribute(conv1_mma,  cudaFuncAttributeMaxDynamicSharedMemorySize, 65536);
    cudaFuncSetAttribute(conv2_poly, cudaFuncAttributeMaxDynamicSharedMemorySize, 2 * STG);
    cudaFuncSetAttribute(conv3_cp,   cudaFuncAttributeMaxDynamicSharedMemorySize, 2 * STG);

    init_kernel<<<1, 128>>>();
    {
        int total = 256*128 + 36*32768;
        wprep_kernel<<<(total + 255) / 256, 256>>>(Wa, W1, W2);
    }
    conv1_mma <<<dim3(128, 2), 256, 65536>>>(waH, waL, ba, S, mHi, mLo);
    conv2_poly<<<256, 512, 2 * STG>>>(w1p, b1, mHi, mLo, g1Hi, g1Lo);
    conv3_cp  <<<256, 512, 2 * STG>>>(w2p, b2, g1Hi, g1Lo, tbuf);

    dot_kernel<<<DTOT / 2048, 256>>>(T, tbuf);
    finalize_kernel<<<1, 1>>>(out);
}